// round 9
// baseline (speedup 1.0000x reference)
#include <cuda_runtime.h>

#define NV 100000
#define NE 600000
#define F 128
#define F2 256
#define NL 5

// scratch (device globals; no allocation allowed)
__device__ float Hbuf[NV * F];
__device__ float Obuf[NV * F];
__device__ float Sum_[F];
__device__ float Sq_[F];
__device__ float Scale_[F];
__device__ float Shift_[F];

// ---- h0 init: h = xe1[x0] + xe2[x1] ----
__global__ void c_init(const int* X, const float* XE1, const float* XE2) {
    long long idx = (long long)blockIdx.x * blockDim.x + threadIdx.x;
    if (idx >= (long long)NV * F) return;
    int v = (int)(idx / F);
    int f = (int)(idx % F);
    int atom = X[2 * v];
    if (atom < 0) atom = 0;
    if (atom > 118) atom = 118;
    int chir = X[2 * v + 1];
    if (chir < 0) chir = 0;
    if (chir > 2) chir = 2;
    Hbuf[idx] = XE1[atom * F + f] + XE2[chir * F + f];
}

// ---- base: Obuf = (1+eps)*H + relu(H + e_self) ----
__global__ void c_base(const float* EE1, const float* EE2, const float* EPS, int l) {
    long long idx = (long long)blockIdx.x * blockDim.x + threadIdx.x;
    if (idx >= (long long)NV * F) return;
    int f = (int)(idx % F);
    float h = Hbuf[idx];
    float e0 = EE1[(l * 5 + 0) * F + f] + EE2[(l * 3 + 0) * F + f];
    float m = h + e0;
    if (m < 0.f) m = 0.f;
    Obuf[idx] = (1.f + EPS[l]) * h + m;
}

// ---- scatter: Obuf[dst] += relu(H[src] + e) ----
__global__ void c_scat(const int* EI, const int* EA,
                       const float* EE1, const float* EE2, int l) {
    long long idx = (long long)blockIdx.x * blockDim.x + threadIdx.x;
    if (idx >= (long long)NE * F) return;
    int e = (int)(idx / F);
    int f = (int)(idx % F);
    int s = EI[e];
    int d = EI[NE + e];
    if (s < 0 || s >= NV || d < 0 || d >= NV) return;
    int b = EA[2 * e];
    if (b < 0) b = 0;
    if (b > 4) b = 4;
    int dr = EA[2 * e + 1];
    if (dr < 0) dr = 0;
    if (dr > 2) dr = 2;
    float m = Hbuf[(long long)s * F + f]
            + EE1[(l * 5 + b) * F + f] + EE2[(l * 3 + dr) * F + f];
    if (m < 0.f) m = 0.f;
    atomicAdd(&Obuf[(long long)d * F + f], m);
}

// ---- MLP: 4 nodes per block. Obuf rows -> lin1(relu) -> lin2 -> Obuf rows ----
__global__ void __launch_bounds__(256) c_mlp4(const float* W1g, const float* B1g,
                                              const float* W2g, const float* B2g,
                                              int l) {
    __shared__ float row[4][F];
    __shared__ float mid[4][F2];
    int v0 = blockIdx.x * 4;
    int t = threadIdx.x;
    // load 4 rows (512 floats, 256 threads -> 2 each)
    for (int j = t; j < 4 * F; j += 256)
        row[j / F][j % F] = Obuf[(long long)(v0 + j / F) * F + (j % F)];
    __syncthreads();
    // lin1: mid[i][t] = relu(b1[t] + sum_k row[i][k]*W1[l][k][t])
    {
        float b = B1g[l * F2 + t];
        float a0 = b, a1 = b, a2 = b, a3 = b;
        const float* w = W1g + (long long)l * F * F2 + t;
        for (int k = 0; k < F; k++) {
            float wv = w[(long long)k * F2];
            a0 += row[0][k] * wv;
            a1 += row[1][k] * wv;
            a2 += row[2][k] * wv;
            a3 += row[3][k] * wv;
        }
        mid[0][t] = a0 < 0.f ? 0.f : a0;
        mid[1][t] = a1 < 0.f ? 0.f : a1;
        mid[2][t] = a2 < 0.f ? 0.f : a2;
        mid[3][t] = a3 < 0.f ? 0.f : a3;
    }
    __syncthreads();
    // lin2: out[i][t] = b2[t] + sum_j mid[i][j]*W2[l][j][t], t in 0..127
    if (t < F) {
        float b = B2g[l * F + t];
        float a0 = b, a1 = b, a2 = b, a3 = b;
        const float* w = W2g + (long long)l * F2 * F + t;
        for (int j = 0; j < F2; j++) {
            float wv = w[(long long)j * F];
            a0 += mid[0][j] * wv;
            a1 += mid[1][j] * wv;
            a2 += mid[2][j] * wv;
            a3 += mid[3][j] * wv;
        }
        Obuf[(long long)(v0 + 0) * F + t] = a0;
        Obuf[(long long)(v0 + 1) * F + t] = a1;
        Obuf[(long long)(v0 + 2) * F + t] = a2;
        Obuf[(long long)(v0 + 3) * F + t] = a3;
    }
}

// ---- BN stats: one block per feature ----
__global__ void c_stats() {
    __shared__ float ssum[256], ssq[256];
    int f = blockIdx.x;  // 0..127
    int t = threadIdx.x; // 256
    float s = 0.f, q = 0.f;
    for (int v = t; v < NV; v += 256) {
        float x = Obuf[(long long)v * F + f];
        s += x;
        q += x * x;
    }
    ssum[t] = s;
    ssq[t] = q;
    __syncthreads();
    for (int off = 128; off > 0; off >>= 1) {
        if (t < off) {
            ssum[t] += ssum[t + off];
            ssq[t] += ssq[t + off];
        }
        __syncthreads();
    }
    if (t == 0) {
        Sum_[f] = ssum[0];
        Sq_[f] = ssq[0];
    }
}

__global__ void c_fin(const float* G, const float* B, int l) {
    int f = threadIdx.x;  // 128
    float mean = Sum_[f] / (float)NV;
    float var = Sq_[f] / (float)NV - mean * mean;
    if (var < 0.f) var = 0.f;
    float rstd = rsqrtf(var + 1e-5f);
    float sc = rstd * G[l * F + f];
    Scale_[f] = sc;
    Shift_[f] = B[l * F + f] - mean * sc;
}

// ---- BN apply. last==0: relu -> Hbuf. last==1: write to dout ----
__global__ void c_apply(float* dout, int last) {
    long long idx = (long long)blockIdx.x * blockDim.x + threadIdx.x;
    if (idx >= (long long)NV * F) return;
    int f = (int)(idx % F);
    float y = Obuf[idx] * Scale_[f] + Shift_[f];
    if (!last) {
        if (y < 0.f) y = 0.f;
        Hbuf[idx] = y;
    } else {
        dout[idx] = y;
    }
}

extern "C" void kernel_launch(void* const* d_in, const int* in_sizes, int n_in,
                              void* d_out, int out_size) {
    const int*   X   = (const int*)d_in[0];
    const int*   EI  = (const int*)d_in[1];
    const int*   EA  = (const int*)d_in[2];
    const float* XE1 = (const float*)d_in[3];
    const float* XE2 = (const float*)d_in[4];
    const float* EE1 = (const float*)d_in[5];
    const float* EE2 = (const float*)d_in[6];
    const float* W1g = (const float*)d_in[7];
    const float* B1g = (const float*)d_in[8];
    const float* W2g = (const float*)d_in[9];
    const float* B2g = (const float*)d_in[10];
    const float* EPS = (const float*)d_in[11];
    const float* G   = (const float*)d_in[12];
    const float* B   = (const float*)d_in[13];
    float* dout = (float*)d_out;

    long long nvf = (long long)NV * F;
    int gb_n = (int)((nvf + 255) / 256);
    long long nef = (long long)NE * F;
    int gb_e = (int)((nef + 255) / 256);

    c_init<<<gb_n, 256>>>(X, XE1, XE2);
    for (int l = 0; l < NL; l++) {
        c_base<<<gb_n, 256>>>(EE1, EE2, EPS, l);
        c_scat<<<gb_e, 256>>>(EI, EA, EE1, EE2, l);
        c_mlp4<<<NV / 4, 256>>>(W1g, B1g, W2g, B2g, l);
        c_stats<<<F, 256>>>();
        c_fin<<<1, F>>>(G, B, l);
        c_apply<<<gb_n, 256>>>(dout, (l == NL - 1) ? 1 : 0);
    }
}

// round 11
// speedup vs baseline: 1.2721x; 1.2721x over previous
#include <cuda_runtime.h>
#include <cuda_bf16.h>
#include <stdint.h>

#define NV 100000
#define NE 600000
#define F 128
#define F2 256
#define NL 5

// ---------------- scratch ----------------
__device__ float Hbuf[NV * F];
__device__ float Obuf[NV * F];
__device__ __nv_bfloat16 MidHi[(size_t)NV * F2];
__device__ __nv_bfloat16 MidLo[(size_t)NV * F2];
__device__ float Sum_[F];
__device__ float Sq_[F];
__device__ float Scale_[F];
__device__ float Shift_[F];

// ================= proven clean-room kernels (unchanged from R9) =================
__global__ void c_init(const int* X, const float* XE1, const float* XE2) {
    long long idx = (long long)blockIdx.x * blockDim.x + threadIdx.x;
    if (idx >= (long long)NV * F) return;
    int v = (int)(idx / F);
    int f = (int)(idx % F);
    int atom = X[2 * v];
    if (atom < 0) atom = 0;
    if (atom > 118) atom = 118;
    int chir = X[2 * v + 1];
    if (chir < 0) chir = 0;
    if (chir > 2) chir = 2;
    Hbuf[idx] = XE1[atom * F + f] + XE2[chir * F + f];
}

__global__ void c_base(const float* EE1, const float* EE2, const float* EPS, int l) {
    long long idx = (long long)blockIdx.x * blockDim.x + threadIdx.x;
    if (idx >= (long long)NV * F) return;
    int f = (int)(idx % F);
    float h = Hbuf[idx];
    float e0 = EE1[(l * 5 + 0) * F + f] + EE2[(l * 3 + 0) * F + f];
    float m = h + e0;
    if (m < 0.f) m = 0.f;
    Obuf[idx] = (1.f + EPS[l]) * h + m;
}

__global__ void c_scat(const int* EI, const int* EA,
                       const float* EE1, const float* EE2, int l) {
    long long idx = (long long)blockIdx.x * blockDim.x + threadIdx.x;
    if (idx >= (long long)NE * F) return;
    int e = (int)(idx / F);
    int f = (int)(idx % F);
    int s = EI[e];
    int d = EI[NE + e];
    if (s < 0 || s >= NV || d < 0 || d >= NV) return;
    int b = EA[2 * e];
    if (b < 0) b = 0;
    if (b > 4) b = 4;
    int dr = EA[2 * e + 1];
    if (dr < 0) dr = 0;
    if (dr > 2) dr = 2;
    float m = Hbuf[(long long)s * F + f]
            + EE1[(l * 5 + b) * F + f] + EE2[(l * 3 + dr) * F + f];
    if (m < 0.f) m = 0.f;
    atomicAdd(&Obuf[(long long)d * F + f], m);
}

__global__ void c_stats() {
    __shared__ float ssum[256], ssq[256];
    int f = blockIdx.x;
    int t = threadIdx.x;
    float s = 0.f, q = 0.f;
    for (int v = t; v < NV; v += 256) {
        float x = Obuf[(long long)v * F + f];
        s += x;
        q += x * x;
    }
    ssum[t] = s;
    ssq[t] = q;
    __syncthreads();
    for (int off = 128; off > 0; off >>= 1) {
        if (t < off) {
            ssum[t] += ssum[t + off];
            ssq[t] += ssq[t + off];
        }
        __syncthreads();
    }
    if (t == 0) {
        Sum_[f] = ssum[0];
        Sq_[f] = ssq[0];
    }
}

__global__ void c_fin(const float* G, const float* B, int l) {
    int f = threadIdx.x;
    float mean = Sum_[f] / (float)NV;
    float var = Sq_[f] / (float)NV - mean * mean;
    if (var < 0.f) var = 0.f;
    float rstd = rsqrtf(var + 1e-5f);
    float sc = rstd * G[l * F + f];
    Scale_[f] = sc;
    Shift_[f] = B[l * F + f] - mean * sc;
}

__global__ void c_apply(float* dout, int last) {
    long long idx = (long long)blockIdx.x * blockDim.x + threadIdx.x;
    if (idx >= (long long)NV * F) return;
    int f = (int)(idx % F);
    float y = Obuf[idx] * Scale_[f] + Shift_[f];
    if (!last) {
        if (y < 0.f) y = 0.f;
        Hbuf[idx] = y;
    } else {
        dout[idx] = y;
    }
}

// ================= mma.sync split-bf16 GEMM =================
__device__ __forceinline__ uint32_t s2u(const void* p) {
    return (uint32_t)__cvta_generic_to_shared(p);
}

__device__ __forceinline__ void ldsm4(uint32_t& r0, uint32_t& r1, uint32_t& r2,
                                      uint32_t& r3, uint32_t a) {
    asm volatile("ldmatrix.sync.aligned.m8n8.x4.shared.b16 {%0,%1,%2,%3}, [%4];"
                 : "=r"(r0), "=r"(r1), "=r"(r2), "=r"(r3) : "r"(a));
}

__device__ __forceinline__ void mmabf(float* c,
                                      uint32_t a0, uint32_t a1, uint32_t a2, uint32_t a3,
                                      uint32_t b0, uint32_t b1) {
    asm volatile(
        "mma.sync.aligned.m16n8k16.row.col.f32.bf16.bf16.f32 "
        "{%0,%1,%2,%3},{%4,%5,%6,%7},{%8,%9},{%0,%1,%2,%3};"
        : "+f"(c[0]), "+f"(c[1]), "+f"(c[2]), "+f"(c[3])
        : "r"(a0), "r"(a1), "r"(a2), "r"(a3), "r"(b0), "r"(b1));
}

__device__ __forceinline__ void splitbf(float v, __nv_bfloat16& h, __nv_bfloat16& lo) {
    h = __float2bfloat16(v);
    lo = __float2bfloat16(v - __bfloat162float(h));
}

extern __shared__ __align__(16) char dsm[];

// ---- GEMM1: MidHi/Lo[NV,256] = split(relu(Obuf[NV,128] @ W1 + b1)) ----
// per CTA: M=64 rows, full N=256, K=128. smem strides padded +16B.
__global__ void __launch_bounds__(256) g1(const float* __restrict__ W1g,
                                          const float* __restrict__ B1g, int l) {
    const int SA = 136;  // elements per row (128 + 8 pad) = 272B
    __nv_bfloat16* AH = (__nv_bfloat16*)dsm;
    __nv_bfloat16* AL = AH + 64 * SA;
    __nv_bfloat16* BH = AL + 64 * SA;
    __nv_bfloat16* BL = BH + 256 * SA;
    int tid = threadIdx.x;
    int row0 = blockIdx.x * 64;

    // stage A (Obuf rows -> split bf16)
    for (int idx = tid; idx < 64 * 128; idx += 256) {
        int m = idx >> 7, k = idx & 127;
        int row = row0 + m;
        float v = (row < NV) ? Obuf[(size_t)row * F + k] : 0.f;
        __nv_bfloat16 h, lo;
        splitbf(v, h, lo);
        AH[m * SA + k] = h;
        AL[m * SA + k] = lo;
    }
    // stage B: W1 [k][n] -> smem [n][k] split
    const float* Wl = W1g + (size_t)l * F * F2;
    for (int idx = tid; idx < 256 * 128; idx += 256) {
        int n = idx & 255, k = idx >> 8;
        float v = Wl[k * F2 + n];
        __nv_bfloat16 h, lo;
        splitbf(v, h, lo);
        BH[n * SA + k] = h;
        BL[n * SA + k] = lo;
    }
    __syncthreads();

    int lane = tid & 31, wid = tid >> 5;
    int wm = wid & 3, wn = wid >> 2;  // warp covers rows wm*16..+15, cols wn*128..+127
    float acc[16][4];
#pragma unroll
    for (int i = 0; i < 16; i++)
#pragma unroll
        for (int j = 0; j < 4; j++) acc[i][j] = 0.f;

    int lrow = lane & 15;
    int lkof = (lane >> 4) * 8;

    for (int ks = 0; ks < 8; ks++) {
        int kk = ks * 16 + lkof;
        uint32_t ah0, ah1, ah2, ah3, al0, al1, al2, al3;
        ldsm4(ah0, ah1, ah2, ah3, s2u(AH + (wm * 16 + lrow) * SA + kk));
        ldsm4(al0, al1, al2, al3, s2u(AL + (wm * 16 + lrow) * SA + kk));
#pragma unroll
        for (int np = 0; np < 8; np++) {
            int nrow = wn * 128 + np * 16 + lrow;
            uint32_t bh0, bh1, bh2, bh3, bl0, bl1, bl2, bl3;
            ldsm4(bh0, bh1, bh2, bh3, s2u(BH + nrow * SA + kk));
            ldsm4(bl0, bl1, bl2, bl3, s2u(BL + nrow * SA + kk));
            mmabf(acc[2 * np], ah0, ah1, ah2, ah3, bh0, bh2);
            mmabf(acc[2 * np], ah0, ah1, ah2, ah3, bl0, bl2);
            mmabf(acc[2 * np], al0, al1, al2, al3, bh0, bh2);
            mmabf(acc[2 * np + 1], ah0, ah1, ah2, ah3, bh1, bh3);
            mmabf(acc[2 * np + 1], ah0, ah1, ah2, ah3, bl1, bl3);
            mmabf(acc[2 * np + 1], al0, al1, al2, al3, bh1, bh3);
        }
    }

    // epilogue: +bias, relu, split, store bf16 pairs
    const float* bias = B1g + l * F2;
    int r = lane >> 2, cp = (lane & 3) * 2;
#pragma unroll
    for (int nt = 0; nt < 16; nt++) {
        int col = wn * 128 + nt * 8 + cp;
        float b0 = __ldg(bias + col), b1 = __ldg(bias + col + 1);
#pragma unroll
        for (int half = 0; half < 2; half++) {
            int row = row0 + wm * 16 + r + half * 8;
            if (row < NV) {
                float v0 = fmaxf(acc[nt][2 * half + 0] + b0, 0.f);
                float v1 = fmaxf(acc[nt][2 * half + 1] + b1, 0.f);
                __nv_bfloat16 h0, l0, h1, l1;
                splitbf(v0, h0, l0);
                splitbf(v1, h1, l1);
                uint32_t hw = (uint32_t)__bfloat16_as_ushort(h0) |
                              ((uint32_t)__bfloat16_as_ushort(h1) << 16);
                uint32_t lw = (uint32_t)__bfloat16_as_ushort(l0) |
                              ((uint32_t)__bfloat16_as_ushort(l1) << 16);
                *(uint32_t*)(MidHi + (size_t)row * F2 + col) = hw;
                *(uint32_t*)(MidLo + (size_t)row * F2 + col) = lw;
            }
        }
    }
}

// ---- GEMM2: Obuf[NV,128] = MidHi/Lo[NV,256] @ W2 + b2 ----
// per CTA: M=64 rows, full N=128, K=256 single-stage.
__global__ void __launch_bounds__(256) g2(const float* __restrict__ W2g,
                                          const float* __restrict__ B2g, int l) {
    const int SA = 264;  // 256 + 8 pad = 528B rows
    __nv_bfloat16* AH = (__nv_bfloat16*)dsm;
    __nv_bfloat16* AL = AH + 64 * SA;
    __nv_bfloat16* BH = AL + 64 * SA;
    __nv_bfloat16* BL = BH + 128 * SA;
    int tid = threadIdx.x;
    int row0 = blockIdx.x * 64;

    // stage A: Mid bf16 already split; copy 4B at a time
    for (int idx = tid; idx < 64 * 128; idx += 256) {
        int m = idx >> 7, k2 = idx & 127;
        int row = row0 + m;
        uint32_t h = 0, lo = 0;
        if (row < NV) {
            h = ((const uint32_t*)MidHi)[(size_t)row * 128 + k2];
            lo = ((const uint32_t*)MidLo)[(size_t)row * 128 + k2];
        }
        *(uint32_t*)(AH + m * SA + 2 * k2) = h;
        *(uint32_t*)(AL + m * SA + 2 * k2) = lo;
    }
    // stage B: W2 [k][n] (256x128) -> smem [n][k] split
    const float* Wl = W2g + (size_t)l * F2 * F;
    for (int idx = tid; idx < 256 * 128; idx += 256) {
        int n = idx & 127, k = idx >> 7;
        float v = Wl[(size_t)k * F + n];
        __nv_bfloat16 h, lo;
        splitbf(v, h, lo);
        BH[n * SA + k] = h;
        BL[n * SA + k] = lo;
    }
    __syncthreads();

    int lane = tid & 31, wid = tid >> 5;
    int wm = wid & 3, wn = wid >> 2;  // cols wn*64..+63
    float acc[8][4];
#pragma unroll
    for (int i = 0; i < 8; i++)
#pragma unroll
        for (int j = 0; j < 4; j++) acc[i][j] = 0.f;

    int lrow = lane & 15;
    int lkof = (lane >> 4) * 8;

    for (int ks = 0; ks < 16; ks++) {
        int kk = ks * 16 + lkof;
        uint32_t ah0, ah1, ah2, ah3, al0, al1, al2, al3;
        ldsm4(ah0, ah1, ah2, ah3, s2u(AH + (wm * 16 + lrow) * SA + kk));
        ldsm4(al0, al1, al2, al3, s2u(AL + (wm * 16 + lrow) * SA + kk));
#pragma unroll
        for (int np = 0; np < 4; np++) {
            int nrow = wn * 64 + np * 16 + lrow;
            uint32_t bh0, bh1, bh2, bh3, bl0, bl1, bl2, bl3;
            ldsm4(bh0, bh1, bh2, bh3, s2u(BH + nrow * SA + kk));
            ldsm4(bl0, bl1, bl2, bl3, s2u(BL + nrow * SA + kk));
            mmabf(acc[2 * np], ah0, ah1, ah2, ah3, bh0, bh2);
            mmabf(acc[2 * np], ah0, ah1, ah2, ah3, bl0, bl2);
            mmabf(acc[2 * np], al0, al1, al2, al3, bh0, bh2);
            mmabf(acc[2 * np + 1], ah0, ah1, ah2, ah3, bh1, bh3);
            mmabf(acc[2 * np + 1], ah0, ah1, ah2, ah3, bl1, bl3);
            mmabf(acc[2 * np + 1], al0, al1, al2, al3, bh1, bh3);
        }
    }

    const float* bias = B2g + l * F;
    int r = lane >> 2, cp = (lane & 3) * 2;
#pragma unroll
    for (int nt = 0; nt < 8; nt++) {
        int col = wn * 64 + nt * 8 + cp;
        float b0 = __ldg(bias + col), b1 = __ldg(bias + col + 1);
#pragma unroll
        for (int half = 0; half < 2; half++) {
            int row = row0 + wm * 16 + r + half * 8;
            if (row < NV) {
                float2 o;
                o.x = acc[nt][2 * half + 0] + b0;
                o.y = acc[nt][2 * half + 1] + b1;
                *(float2*)(Obuf + (size_t)row * F + col) = o;
            }
        }
    }
}

// ================= launch =================
extern "C" void kernel_launch(void* const* d_in, const int* in_sizes, int n_in,
                              void* d_out, int out_size) {
    const int*   X   = (const int*)d_in[0];
    const int*   EI  = (const int*)d_in[1];
    const int*   EA  = (const int*)d_in[2];
    const float* XE1 = (const float*)d_in[3];
    const float* XE2 = (const float*)d_in[4];
    const float* EE1 = (const float*)d_in[5];
    const float* EE2 = (const float*)d_in[6];
    const float* W1g = (const float*)d_in[7];
    const float* B1g = (const float*)d_in[8];
    const float* W2g = (const float*)d_in[9];
    const float* B2g = (const float*)d_in[10];
    const float* EPS = (const float*)d_in[11];
    const float* G   = (const float*)d_in[12];
    const float* B   = (const float*)d_in[13];
    float* dout = (float*)d_out;

    const int SM1 = (64 * 136 * 2 + 256 * 136 * 2) * 2;  // 174080 B
    const int SM2 = (64 * 264 * 2 + 128 * 264 * 2) * 2;  // 202752 B
    cudaFuncSetAttribute(g1, cudaFuncAttributeMaxDynamicSharedMemorySize, SM1);
    cudaFuncSetAttribute(g2, cudaFuncAttributeMaxDynamicSharedMemorySize, SM2);

    long long nvf = (long long)NV * F;
    int gb_n = (int)((nvf + 255) / 256);
    long long nef = (long long)NE * F;
    int gb_e = (int)((nef + 255) / 256);
    int gb_g = (NV + 63) / 64;  // 1563

    c_init<<<gb_n, 256>>>(X, XE1, XE2);
    for (int l = 0; l < NL; l++) {
        c_base<<<gb_n, 256>>>(EE1, EE2, EPS, l);
        c_scat<<<gb_e, 256>>>(EI, EA, EE1, EE2, l);
        g1<<<gb_g, 256, SM1>>>(W1g, B1g, l);
        g2<<<gb_g, 256, SM2>>>(W2g, B2g, l);
        c_stats<<<F, 256>>>();
        c_fin<<<1, F>>>(G, B, l);
        c_apply<<<gb_n, 256>>>(dout, (l == NL - 1) ? 1 : 0);
    }
}

// round 12
// speedup vs baseline: 1.4888x; 1.1704x over previous
#include <cuda_runtime.h>
#include <cuda_bf16.h>
#include <stdint.h>

#define NV 100000
#define NE 600000
#define F 128
#define F2 256
#define NL 5

// ---------------- scratch ----------------
__device__ float Hbuf[NV * F];
__device__ float Obuf[NV * F];
__device__ __nv_bfloat16 MidHi[(size_t)NV * F2];
__device__ __nv_bfloat16 MidLo[(size_t)NV * F2];
__device__ float Sum_[F];
__device__ float Sq_[F];
__device__ float Scale_[F];
__device__ float Shift_[F];
// pre-split transposed weights: W1 as [l][n=256][k=128], W2 as [l][n=128][k=256]
__device__ __nv_bfloat16 W1Ht[NL * F2 * F];
__device__ __nv_bfloat16 W1Lt[NL * F2 * F];
__device__ __nv_bfloat16 W2Ht[NL * F * F2];
__device__ __nv_bfloat16 W2Lt[NL * F * F2];

__device__ __forceinline__ void splitbf(float v, __nv_bfloat16& h, __nv_bfloat16& lo) {
    h = __float2bfloat16(v);
    lo = __float2bfloat16(v - __bfloat162float(h));
}

// ================= proven clean-room kernels =================
__global__ void c_init(const int* X, const float* XE1, const float* XE2) {
    long long idx = (long long)blockIdx.x * blockDim.x + threadIdx.x;
    if (idx >= (long long)NV * F) return;
    int v = (int)(idx / F);
    int f = (int)(idx % F);
    int atom = X[2 * v];
    if (atom < 0) atom = 0;
    if (atom > 118) atom = 118;
    int chir = X[2 * v + 1];
    if (chir < 0) chir = 0;
    if (chir > 2) chir = 2;
    Hbuf[idx] = XE1[atom * F + f] + XE2[chir * F + f];
}

__global__ void c_base(const float* EE1, const float* EE2, const float* EPS, int l) {
    long long idx = (long long)blockIdx.x * blockDim.x + threadIdx.x;
    if (idx >= (long long)NV * F) return;
    int f = (int)(idx % F);
    float h = Hbuf[idx];
    float e0 = EE1[(l * 5 + 0) * F + f] + EE2[(l * 3 + 0) * F + f];
    float m = h + e0;
    if (m < 0.f) m = 0.f;
    Obuf[idx] = (1.f + EPS[l]) * h + m;
}

__global__ void c_scat(const int* EI, const int* EA,
                       const float* EE1, const float* EE2, int l) {
    long long idx = (long long)blockIdx.x * blockDim.x + threadIdx.x;
    if (idx >= (long long)NE * F) return;
    int e = (int)(idx / F);
    int f = (int)(idx % F);
    int s = EI[e];
    int d = EI[NE + e];
    if (s < 0 || s >= NV || d < 0 || d >= NV) return;
    int b = EA[2 * e];
    if (b < 0) b = 0;
    if (b > 4) b = 4;
    int dr = EA[2 * e + 1];
    if (dr < 0) dr = 0;
    if (dr > 2) dr = 2;
    float m = Hbuf[(long long)s * F + f]
            + EE1[(l * 5 + b) * F + f] + EE2[(l * 3 + dr) * F + f];
    if (m < 0.f) m = 0.f;
    atomicAdd(&Obuf[(long long)d * F + f], m);
}

__global__ void c_stats() {
    __shared__ float ssum[256], ssq[256];
    int f = blockIdx.x;
    int t = threadIdx.x;
    float s = 0.f, q = 0.f;
    for (int v = t; v < NV; v += 256) {
        float x = Obuf[(long long)v * F + f];
        s += x;
        q += x * x;
    }
    ssum[t] = s;
    ssq[t] = q;
    __syncthreads();
    for (int off = 128; off > 0; off >>= 1) {
        if (t < off) {
            ssum[t] += ssum[t + off];
            ssq[t] += ssq[t + off];
        }
        __syncthreads();
    }
    if (t == 0) {
        Sum_[f] = ssum[0];
        Sq_[f] = ssq[0];
    }
}

__global__ void c_fin(const float* G, const float* B, int l) {
    int f = threadIdx.x;
    float mean = Sum_[f] / (float)NV;
    float var = Sq_[f] / (float)NV - mean * mean;
    if (var < 0.f) var = 0.f;
    float rstd = rsqrtf(var + 1e-5f);
    float sc = rstd * G[l * F + f];
    Scale_[f] = sc;
    Shift_[f] = B[l * F + f] - mean * sc;
}

// fused: BN-apply(relu) of layer l -> Hbuf, then base of layer lnext -> Obuf
__global__ void c_apbase(const float* EE1, const float* EE2, const float* EPS,
                         int lnext) {
    long long idx = (long long)blockIdx.x * blockDim.x + threadIdx.x;
    if (idx >= (long long)NV * F) return;
    int f = (int)(idx % F);
    float y = Obuf[idx] * Scale_[f] + Shift_[f];
    float h = y < 0.f ? 0.f : y;
    Hbuf[idx] = h;
    float e0 = EE1[(lnext * 5 + 0) * F + f] + EE2[(lnext * 3 + 0) * F + f];
    float m = h + e0;
    if (m < 0.f) m = 0.f;
    Obuf[idx] = (1.f + EPS[lnext]) * h + m;
}

__global__ void c_apply_last(float* dout) {
    long long idx = (long long)blockIdx.x * blockDim.x + threadIdx.x;
    if (idx >= (long long)NV * F) return;
    int f = (int)(idx % F);
    dout[idx] = Obuf[idx] * Scale_[f] + Shift_[f];
}

// ================= weight pre-split (once per launch) =================
__global__ void w_prep(const float* W1g, const float* W2g) {
    int idx = blockIdx.x * blockDim.x + threadIdx.x;
    if (idx < NL * F * F2) {
        // W1: [l][k=128][n=256] -> [l][n][k]
        int l = idx / (F * F2);
        int rem = idx % (F * F2);
        int k = rem / F2, n = rem % F2;
        __nv_bfloat16 h, lo;
        splitbf(W1g[idx], h, lo);
        W1Ht[((size_t)l * F2 + n) * F + k] = h;
        W1Lt[((size_t)l * F2 + n) * F + k] = lo;
        // W2: [l][k=256][n=128] -> [l][n][k]
        int k2 = rem / F, n2 = rem % F;
        splitbf(W2g[idx], h, lo);
        W2Ht[((size_t)l * F + n2) * F2 + k2] = h;
        W2Lt[((size_t)l * F + n2) * F2 + k2] = lo;
    }
}

// ================= mma.sync split-bf16 GEMM =================
__device__ __forceinline__ uint32_t s2u(const void* p) {
    return (uint32_t)__cvta_generic_to_shared(p);
}

__device__ __forceinline__ void ldsm4(uint32_t& r0, uint32_t& r1, uint32_t& r2,
                                      uint32_t& r3, uint32_t a) {
    asm volatile("ldmatrix.sync.aligned.m8n8.x4.shared.b16 {%0,%1,%2,%3}, [%4];"
                 : "=r"(r0), "=r"(r1), "=r"(r2), "=r"(r3) : "r"(a));
}

__device__ __forceinline__ void mmabf(float* c,
                                      uint32_t a0, uint32_t a1, uint32_t a2, uint32_t a3,
                                      uint32_t b0, uint32_t b1) {
    asm volatile(
        "mma.sync.aligned.m16n8k16.row.col.f32.bf16.bf16.f32 "
        "{%0,%1,%2,%3},{%4,%5,%6,%7},{%8,%9},{%0,%1,%2,%3};"
        : "+f"(c[0]), "+f"(c[1]), "+f"(c[2]), "+f"(c[3])
        : "r"(a0), "r"(a1), "r"(a2), "r"(a3), "r"(b0), "r"(b1));
}

extern __shared__ __align__(16) char dsm[];

// ---- GEMM1: Mid split = relu(Obuf @ W1 + b1). CTA: M=32, N=128 (grid.y half) ----
__global__ void __launch_bounds__(256) g1(const float* __restrict__ B1g, int l) {
    const int SA = 136;
    __nv_bfloat16* AH = (__nv_bfloat16*)dsm;      // 32*136
    __nv_bfloat16* AL = AH + 32 * SA;
    __nv_bfloat16* BH = AL + 32 * SA;             // 128*136
    __nv_bfloat16* BL = BH + 128 * SA;
    int tid = threadIdx.x;
    int row0 = blockIdx.x * 32;
    int ncol0 = blockIdx.y * 128;

    // stage A (Obuf f32 -> split)
    for (int idx = tid; idx < 32 * 128; idx += 256) {
        int m = idx >> 7, k = idx & 127;
        int row = row0 + m;
        float v = (row < NV) ? Obuf[(size_t)row * F + k] : 0.f;
        __nv_bfloat16 h, lo;
        splitbf(v, h, lo);
        AH[m * SA + k] = h;
        AL[m * SA + k] = lo;
    }
    // stage B (pre-split bf16, coalesced uint32 copies)
    {
        const uint32_t* WH = (const uint32_t*)W1Ht + ((size_t)l * F2 + ncol0) * 64;
        const uint32_t* WL = (const uint32_t*)W1Lt + ((size_t)l * F2 + ncol0) * 64;
        uint32_t* BH32 = (uint32_t*)BH;
        uint32_t* BL32 = (uint32_t*)BL;
        for (int idx = tid; idx < 128 * 64; idx += 256) {
            int n = idx >> 6, k2 = idx & 63;
            BH32[n * 68 + k2] = WH[n * 64 + k2];
            BL32[n * 68 + k2] = WL[n * 64 + k2];
        }
    }
    __syncthreads();

    int lane = tid & 31, wid = tid >> 5;
    int wm = wid & 1, wn = wid >> 1;   // warp: rows wm*16..+15, cols wn*32..+31
    float acc[4][4];
#pragma unroll
    for (int i = 0; i < 4; i++)
#pragma unroll
        for (int j = 0; j < 4; j++) acc[i][j] = 0.f;

    int lrow = lane & 15, lkof = (lane >> 4) * 8;

#pragma unroll
    for (int ks = 0; ks < 8; ks++) {
        int kk = ks * 16 + lkof;
        uint32_t ah0, ah1, ah2, ah3, al0, al1, al2, al3;
        ldsm4(ah0, ah1, ah2, ah3, s2u(AH + (wm * 16 + lrow) * SA + kk));
        ldsm4(al0, al1, al2, al3, s2u(AL + (wm * 16 + lrow) * SA + kk));
#pragma unroll
        for (int np = 0; np < 2; np++) {
            int nrow = wn * 32 + np * 16 + lrow;
            uint32_t bh0, bh1, bh2, bh3, bl0, bl1, bl2, bl3;
            ldsm4(bh0, bh1, bh2, bh3, s2u(BH + nrow * SA + kk));
            ldsm4(bl0, bl1, bl2, bl3, s2u(BL + nrow * SA + kk));
            mmabf(acc[2 * np], ah0, ah1, ah2, ah3, bh0, bh2);
            mmabf(acc[2 * np], ah0, ah1, ah2, ah3, bl0, bl2);
            mmabf(acc[2 * np], al0, al1, al2, al3, bh0, bh2);
            mmabf(acc[2 * np + 1], ah0, ah1, ah2, ah3, bh1, bh3);
            mmabf(acc[2 * np + 1], ah0, ah1, ah2, ah3, bl1, bl3);
            mmabf(acc[2 * np + 1], al0, al1, al2, al3, bh1, bh3);
        }
    }

    const float* bias = B1g + l * F2;
    int r = lane >> 2, cp = (lane & 3) * 2;
#pragma unroll
    for (int nt = 0; nt < 4; nt++) {
        int col = ncol0 + wn * 32 + nt * 8 + cp;
        float b0 = __ldg(bias + col), b1 = __ldg(bias + col + 1);
#pragma unroll
        for (int half = 0; half < 2; half++) {
            int row = row0 + wm * 16 + r + half * 8;
            if (row < NV) {
                float v0 = fmaxf(acc[nt][2 * half + 0] + b0, 0.f);
                float v1 = fmaxf(acc[nt][2 * half + 1] + b1, 0.f);
                __nv_bfloat16 h0, l0, h1, l1;
                splitbf(v0, h0, l0);
                splitbf(v1, h1, l1);
                uint32_t hw = (uint32_t)__bfloat16_as_ushort(h0) |
                              ((uint32_t)__bfloat16_as_ushort(h1) << 16);
                uint32_t lw = (uint32_t)__bfloat16_as_ushort(l0) |
                              ((uint32_t)__bfloat16_as_ushort(l1) << 16);
                *(uint32_t*)(MidHi + (size_t)row * F2 + col) = hw;
                *(uint32_t*)(MidLo + (size_t)row * F2 + col) = lw;
            }
        }
    }
}

// ---- GEMM2: Obuf = Mid @ W2 + b2. CTA: M=64, N=128, K=256 in 2 restaged passes ----
__global__ void __launch_bounds__(256) g2(const float* __restrict__ B2g, int l) {
    const int SA = 136;
    __nv_bfloat16* AH = (__nv_bfloat16*)dsm;      // 64*136
    __nv_bfloat16* AL = AH + 64 * SA;
    __nv_bfloat16* BH = AL + 64 * SA;             // 128*136
    __nv_bfloat16* BL = BH + 128 * SA;
    int tid = threadIdx.x;
    int row0 = blockIdx.x * 64;
    int lane = tid & 31, wid = tid >> 5;
    int wm = wid & 1, wn = wid >> 1;   // warp: rows wm*32..+31, cols wn*32..+31
    int lrow = lane & 15, lkof = (lane >> 4) * 8;

    float acc[2][4][4];
#pragma unroll
    for (int a = 0; a < 2; a++)
#pragma unroll
        for (int i = 0; i < 4; i++)
#pragma unroll
            for (int j = 0; j < 4; j++) acc[a][i][j] = 0.f;

    for (int pass = 0; pass < 2; pass++) {
        if (pass) __syncthreads();
        // stage A: Mid bf16 (already split), K-slice
        {
            const uint32_t* MH = (const uint32_t*)MidHi;
            const uint32_t* ML = (const uint32_t*)MidLo;
            uint32_t* AH32 = (uint32_t*)AH;
            uint32_t* AL32 = (uint32_t*)AL;
            for (int idx = tid; idx < 64 * 64; idx += 256) {
                int m = idx >> 6, k2 = idx & 63;
                int row = row0 + m;
                uint32_t h = 0, lo = 0;
                if (row < NV) {
                    h = MH[(size_t)row * 128 + pass * 64 + k2];
                    lo = ML[(size_t)row * 128 + pass * 64 + k2];
                }
                AH32[m * 68 + k2] = h;
                AL32[m * 68 + k2] = lo;
            }
        }
        // stage B: pre-split W2 [n=128][k=256], slice
        {
            const uint32_t* WH = (const uint32_t*)W2Ht + (size_t)l * F * 128;
            const uint32_t* WL = (const uint32_t*)W2Lt + (size_t)l * F * 128;
            uint32_t* BH32 = (uint32_t*)BH;
            uint32_t* BL32 = (uint32_t*)BL;
            for (int idx = tid; idx < 128 * 64; idx += 256) {
                int n = idx >> 6, k2 = idx & 63;
                BH32[n * 68 + k2] = WH[n * 128 + pass * 64 + k2];
                BL32[n * 68 + k2] = WL[n * 128 + pass * 64 + k2];
            }
        }
        __syncthreads();

#pragma unroll
        for (int ks = 0; ks < 8; ks++) {
            int kk = ks * 16 + lkof;
#pragma unroll
            for (int mt = 0; mt < 2; mt++) {
                uint32_t ah0, ah1, ah2, ah3, al0, al1, al2, al3;
                ldsm4(ah0, ah1, ah2, ah3,
                      s2u(AH + (wm * 32 + mt * 16 + lrow) * SA + kk));
                ldsm4(al0, al1, al2, al3,
                      s2u(AL + (wm * 32 + mt * 16 + lrow) * SA + kk));
#pragma unroll
                for (int np = 0; np < 2; np++) {
                    int nrow = wn * 32 + np * 16 + lrow;
                    uint32_t bh0, bh1, bh2, bh3, bl0, bl1, bl2, bl3;
                    ldsm4(bh0, bh1, bh2, bh3, s2u(BH + nrow * SA + kk));
                    ldsm4(bl0, bl1, bl2, bl3, s2u(BL + nrow * SA + kk));
                    mmabf(acc[mt][2 * np], ah0, ah1, ah2, ah3, bh0, bh2);
                    mmabf(acc[mt][2 * np], ah0, ah1, ah2, ah3, bl0, bl2);
                    mmabf(acc[mt][2 * np], al0, al1, al2, al3, bh0, bh2);
                    mmabf(acc[mt][2 * np + 1], ah0, ah1, ah2, ah3, bh1, bh3);
                    mmabf(acc[mt][2 * np + 1], ah0, ah1, ah2, ah3, bl1, bl3);
                    mmabf(acc[mt][2 * np + 1], al0, al1, al2, al3, bh1, bh3);
                }
            }
        }
    }

    const float* bias = B2g + l * F;
    int r = lane >> 2, cp = (lane & 3) * 2;
#pragma unroll
    for (int mt = 0; mt < 2; mt++) {
#pragma unroll
        for (int nt = 0; nt < 4; nt++) {
            int col = wn * 32 + nt * 8 + cp;
            float b0 = __ldg(bias + col), b1 = __ldg(bias + col + 1);
#pragma unroll
            for (int half = 0; half < 2; half++) {
                int row = row0 + wm * 32 + mt * 16 + r + half * 8;
                if (row < NV) {
                    float2 o;
                    o.x = acc[mt][nt][2 * half + 0] + b0;
                    o.y = acc[mt][nt][2 * half + 1] + b1;
                    *(float2*)(Obuf + (size_t)row * F + col) = o;
                }
            }
        }
    }
}

// ================= launch =================
extern "C" void kernel_launch(void* const* d_in, const int* in_sizes, int n_in,
                              void* d_out, int out_size) {
    const int*   X   = (const int*)d_in[0];
    const int*   EI  = (const int*)d_in[1];
    const int*   EA  = (const int*)d_in[2];
    const float* XE1 = (const float*)d_in[3];
    const float* XE2 = (const float*)d_in[4];
    const float* EE1 = (const float*)d_in[5];
    const float* EE2 = (const float*)d_in[6];
    const float* W1g = (const float*)d_in[7];
    const float* B1g = (const float*)d_in[8];
    const float* W2g = (const float*)d_in[9];
    const float* B2g = (const float*)d_in[10];
    const float* EPS = (const float*)d_in[11];
    const float* G   = (const float*)d_in[12];
    const float* B   = (const float*)d_in[13];
    float* dout = (float*)d_out;

    const int SM1 = (32 * 136 * 2 + 128 * 136 * 2) * 2;  // 87040 B
    const int SM2 = (64 * 136 * 2 + 128 * 136 * 2) * 2;  // 104448 B
    cudaFuncSetAttribute(g1, cudaFuncAttributeMaxDynamicSharedMemorySize, SM1);
    cudaFuncSetAttribute(g2, cudaFuncAttributeMaxDynamicSharedMemorySize, SM2);

    long long nvf = (long long)NV * F;
    int gb_n = (int)((nvf + 255) / 256);
    long long nef = (long long)NE * F;
    int gb_e = (int)((nef + 255) / 256);

    w_prep<<<(NL * F * F2 + 255) / 256, 256>>>(W1g, W2g);
    c_init<<<gb_n, 256>>>(X, XE1, XE2);
    c_base<<<gb_n, 256>>>(EE1, EE2, EPS, 0);
    dim3 grid1((NV + 31) / 32, 2);
    int grid2 = (NV + 63) / 64;
    for (int l = 0; l < NL; l++) {
        c_scat<<<gb_e, 256>>>(EI, EA, EE1, EE2, l);
        g1<<<grid1, 256, SM1>>>(B1g, l);
        g2<<<grid2, 256, SM2>>>(B2g, l);
        c_stats<<<F, 256>>>();
        c_fin<<<1, F>>>(G, B, l);
        if (l < NL - 1)
            c_apbase<<<gb_n, 256>>>(EE1, EE2, EPS, l + 1);
        else
            c_apply_last<<<gb_n, 256>>>(dout);
    }
}

// round 13
// speedup vs baseline: 2.1475x; 1.4424x over previous
#include <cuda_runtime.h>
#include <cuda_bf16.h>
#include <stdint.h>

#define NV 100000
#define NE 600000
#define F 128
#define F2 256
#define NL 5

// ---------------- scratch ----------------
__device__ float Hbuf[NV * F];
__device__ float Obuf[NV * F];
__device__ __nv_bfloat16 MidHi[(size_t)NV * F2];
__device__ __nv_bfloat16 MidLo[(size_t)NV * F2];
__device__ float Sum_[F];
__device__ float Sq_[F];
__device__ float Scale_[F];
__device__ float Shift_[F];
__device__ __nv_bfloat16 W1Ht[NL * F2 * F];
__device__ __nv_bfloat16 W1Lt[NL * F2 * F];
__device__ __nv_bfloat16 W2Ht[NL * F * F2];
__device__ __nv_bfloat16 W2Lt[NL * F * F2];
// CSR by destination
__device__ int g_cnt[NV];
__device__ int g_cursor[NV];
__device__ int g_rowptr[NV + 1];
__device__ int g_bsum[128];
__device__ int g_boff[128];
__device__ int g_elist[NE];   // src | code<<20

__device__ __forceinline__ void splitbf(float v, __nv_bfloat16& h, __nv_bfloat16& lo) {
    h = __float2bfloat16(v);
    lo = __float2bfloat16(v - __bfloat162float(h));
}

// ================= init / CSR build (exonerated designs from R2) =================
__global__ void c_init(const int* X, const float* XE1, const float* XE2) {
    long long idx = (long long)blockIdx.x * blockDim.x + threadIdx.x;
    if (idx >= (long long)NV * F) return;
    int v = (int)(idx / F);
    int f = (int)(idx % F);
    int atom = X[2 * v];
    if (atom < 0) atom = 0;
    if (atom > 118) atom = 118;
    int chir = X[2 * v + 1];
    if (chir < 0) chir = 0;
    if (chir > 2) chir = 2;
    Hbuf[idx] = XE1[atom * F + f] + XE2[chir * F + f];
}

__global__ void z_zero() {
    int i = blockIdx.x * blockDim.x + threadIdx.x;
    if (i < NV) g_cnt[i] = 0;
}

__global__ void z_count(const int* EI) {
    int e = blockIdx.x * blockDim.x + threadIdx.x;
    if (e >= NE) return;
    int d = EI[NE + e];
    if (d < 0) d = 0;
    if (d >= NV) d = NV - 1;
    atomicAdd(&g_cnt[d], 1);
}

__global__ void z_scan1() {
    __shared__ int s[1024];
    int t = threadIdx.x;
    int gi = blockIdx.x * 1024 + t;
    int v = (gi < NV) ? g_cnt[gi] : 0;
    s[t] = v;
    __syncthreads();
    for (int off = 1; off < 1024; off <<= 1) {
        int xv = 0;
        if (t >= off) xv = s[t - off];
        __syncthreads();
        s[t] += xv;
        __syncthreads();
    }
    if (gi < NV) g_cursor[gi] = s[t] - v;
    if (t == 1023) g_bsum[blockIdx.x] = s[t];
}

__global__ void z_scan2(int nb) {
    __shared__ int s[128];
    int t = threadIdx.x;
    int v = (t < nb) ? g_bsum[t] : 0;
    s[t] = v;
    __syncthreads();
    for (int off = 1; off < 128; off <<= 1) {
        int xv = 0;
        if (t >= off) xv = s[t - off];
        __syncthreads();
        s[t] += xv;
        __syncthreads();
    }
    g_boff[t] = s[t] - v;
    if (t == 0) g_rowptr[NV] = NE;
}

__global__ void z_scan3() {
    int i = blockIdx.x * blockDim.x + threadIdx.x;
    if (i >= NV) return;
    int rp = g_cursor[i] + g_boff[i >> 10];
    g_rowptr[i] = rp;
    g_cursor[i] = rp;
}

__global__ void z_scatter(const int* EI, const int* EA) {
    int e = blockIdx.x * blockDim.x + threadIdx.x;
    if (e >= NE) return;
    int d = EI[NE + e];
    if (d < 0) d = 0;
    if (d >= NV) d = NV - 1;
    int pos = atomicAdd(&g_cursor[d], 1);
    if (pos < 0) pos = 0;
    if (pos >= NE) pos = NE - 1;
    int s = EI[e];
    if (s < 0) s = 0;
    if (s >= NV) s = NV - 1;
    int b = EA[2 * e];
    if (b < 0) b = 0;
    if (b > 4) b = 4;
    int dr = EA[2 * e + 1];
    if (dr < 0) dr = 0;
    if (dr > 2) dr = 2;
    g_elist[pos] = s | ((b * 3 + dr) << 20);
}

// ================= per-layer aggregation: warp-per-node CSR gather =================
// Obuf[v] = (1+eps)*H[v] + relu(H[v]+e0) + sum_in-edges relu(H[src]+e(code))
__global__ void __launch_bounds__(256) k_agg(const float* __restrict__ EE1,
                                             const float* __restrict__ EE2,
                                             const float* __restrict__ EPS, int l) {
    __shared__ __align__(16) float etab[15 * F];
    int t = threadIdx.x;
    for (int j = t; j < 15 * F; j += 256) {
        int c = j >> 7, f = j & 127;
        etab[j] = EE1[(l * 5 + c / 3) * F + f] + EE2[(l * 3 + c % 3) * F + f];
    }
    __syncthreads();
    int gw = blockIdx.x * 8 + (t >> 5);
    int lane = t & 31;
    if (gw >= NV) return;
    float ep1 = 1.0f + EPS[l];
    const float4* hv = (const float4*)Hbuf;
    const float4* et = (const float4*)etab;
    float4 hn = hv[(size_t)gw * 32 + lane];
    float4 e0 = et[lane];
    float4 acc;
    acc.x = ep1 * hn.x + fmaxf(hn.x + e0.x, 0.f);
    acc.y = ep1 * hn.y + fmaxf(hn.y + e0.y, 0.f);
    acc.z = ep1 * hn.z + fmaxf(hn.z + e0.z, 0.f);
    acc.w = ep1 * hn.w + fmaxf(hn.w + e0.w, 0.f);
    int beg = g_rowptr[gw];
    int end = g_rowptr[gw + 1];
    if (beg < 0) beg = 0;
    if (end > NE) end = NE;
    for (int idx = beg; idx < end; idx++) {
        int p = g_elist[idx];
        int src = p & 0xFFFFF;
        int code = (p >> 20) & 15;
        if (src >= NV) src = NV - 1;
        if (code > 14) code = 14;
        float4 h4 = __ldg(&hv[(size_t)src * 32 + lane]);
        float4 ev = et[code * 32 + lane];
        acc.x += fmaxf(h4.x + ev.x, 0.f);
        acc.y += fmaxf(h4.y + ev.y, 0.f);
        acc.z += fmaxf(h4.z + ev.z, 0.f);
        acc.w += fmaxf(h4.w + ev.w, 0.f);
    }
    ((float4*)Obuf)[(size_t)gw * 32 + lane] = acc;
}

// ================= BN =================
__global__ void c_stats() {
    __shared__ float ssum[256], ssq[256];
    int f = blockIdx.x;
    int t = threadIdx.x;
    float s = 0.f, q = 0.f;
    for (int v = t; v < NV; v += 256) {
        float x = Obuf[(long long)v * F + f];
        s += x;
        q += x * x;
    }
    ssum[t] = s;
    ssq[t] = q;
    __syncthreads();
    for (int off = 128; off > 0; off >>= 1) {
        if (t < off) {
            ssum[t] += ssum[t + off];
            ssq[t] += ssq[t + off];
        }
        __syncthreads();
    }
    if (t == 0) {
        Sum_[f] = ssum[0];
        Sq_[f] = ssq[0];
    }
}

__global__ void c_fin(const float* G, const float* B, int l) {
    int f = threadIdx.x;
    float mean = Sum_[f] / (float)NV;
    float var = Sq_[f] / (float)NV - mean * mean;
    if (var < 0.f) var = 0.f;
    float rstd = rsqrtf(var + 1e-5f);
    float sc = rstd * G[l * F + f];
    Scale_[f] = sc;
    Shift_[f] = B[l * F + f] - mean * sc;
}

__global__ void c_apply(float* dout, int last) {
    long long idx = (long long)blockIdx.x * blockDim.x + threadIdx.x;
    if (idx >= (long long)NV * F) return;
    int f = (int)(idx % F);
    float y = Obuf[idx] * Scale_[f] + Shift_[f];
    if (!last) {
        if (y < 0.f) y = 0.f;
        Hbuf[idx] = y;
    } else {
        dout[idx] = y;
    }
}

// ================= weight pre-split =================
__global__ void w_prep(const float* W1g, const float* W2g) {
    int idx = blockIdx.x * blockDim.x + threadIdx.x;
    if (idx < NL * F * F2) {
        int l = idx / (F * F2);
        int rem = idx % (F * F2);
        int k = rem / F2, n = rem % F2;
        __nv_bfloat16 h, lo;
        splitbf(W1g[idx], h, lo);
        W1Ht[((size_t)l * F2 + n) * F + k] = h;
        W1Lt[((size_t)l * F2 + n) * F + k] = lo;
        int k2 = rem / F, n2 = rem % F;
        splitbf(W2g[idx], h, lo);
        W2Ht[((size_t)l * F + n2) * F2 + k2] = h;
        W2Lt[((size_t)l * F + n2) * F2 + k2] = lo;
    }
}

// ================= mma.sync split-bf16 GEMM (unchanged from R12) =================
__device__ __forceinline__ uint32_t s2u(const void* p) {
    return (uint32_t)__cvta_generic_to_shared(p);
}

__device__ __forceinline__ void ldsm4(uint32_t& r0, uint32_t& r1, uint32_t& r2,
                                      uint32_t& r3, uint32_t a) {
    asm volatile("ldmatrix.sync.aligned.m8n8.x4.shared.b16 {%0,%1,%2,%3}, [%4];"
                 : "=r"(r0), "=r"(r1), "=r"(r2), "=r"(r3) : "r"(a));
}

__device__ __forceinline__ void mmabf(float* c,
                                      uint32_t a0, uint32_t a1, uint32_t a2, uint32_t a3,
                                      uint32_t b0, uint32_t b1) {
    asm volatile(
        "mma.sync.aligned.m16n8k16.row.col.f32.bf16.bf16.f32 "
        "{%0,%1,%2,%3},{%4,%5,%6,%7},{%8,%9},{%0,%1,%2,%3};"
        : "+f"(c[0]), "+f"(c[1]), "+f"(c[2]), "+f"(c[3])
        : "r"(a0), "r"(a1), "r"(a2), "r"(a3), "r"(b0), "r"(b1));
}

extern __shared__ __align__(16) char dsm[];

__global__ void __launch_bounds__(256) g1(const float* __restrict__ B1g, int l) {
    const int SA = 136;
    __nv_bfloat16* AH = (__nv_bfloat16*)dsm;
    __nv_bfloat16* AL = AH + 32 * SA;
    __nv_bfloat16* BH = AL + 32 * SA;
    __nv_bfloat16* BL = BH + 128 * SA;
    int tid = threadIdx.x;
    int row0 = blockIdx.x * 32;
    int ncol0 = blockIdx.y * 128;

    for (int idx = tid; idx < 32 * 128; idx += 256) {
        int m = idx >> 7, k = idx & 127;
        int row = row0 + m;
        float v = (row < NV) ? Obuf[(size_t)row * F + k] : 0.f;
        __nv_bfloat16 h, lo;
        splitbf(v, h, lo);
        AH[m * SA + k] = h;
        AL[m * SA + k] = lo;
    }
    {
        const uint32_t* WH = (const uint32_t*)W1Ht + ((size_t)l * F2 + ncol0) * 64;
        const uint32_t* WL = (const uint32_t*)W1Lt + ((size_t)l * F2 + ncol0) * 64;
        uint32_t* BH32 = (uint32_t*)BH;
        uint32_t* BL32 = (uint32_t*)BL;
        for (int idx = tid; idx < 128 * 64; idx += 256) {
            int n = idx >> 6, k2 = idx & 63;
            BH32[n * 68 + k2] = WH[n * 64 + k2];
            BL32[n * 68 + k2] = WL[n * 64 + k2];
        }
    }
    __syncthreads();

    int lane = tid & 31, wid = tid >> 5;
    int wm = wid & 1, wn = wid >> 1;
    float acc[4][4];
#pragma unroll
    for (int i = 0; i < 4; i++)
#pragma unroll
        for (int j = 0; j < 4; j++) acc[i][j] = 0.f;

    int lrow = lane & 15, lkof = (lane >> 4) * 8;

#pragma unroll
    for (int ks = 0; ks < 8; ks++) {
        int kk = ks * 16 + lkof;
        uint32_t ah0, ah1, ah2, ah3, al0, al1, al2, al3;
        ldsm4(ah0, ah1, ah2, ah3, s2u(AH + (wm * 16 + lrow) * SA + kk));
        ldsm4(al0, al1, al2, al3, s2u(AL + (wm * 16 + lrow) * SA + kk));
#pragma unroll
        for (int np = 0; np < 2; np++) {
            int nrow = wn * 32 + np * 16 + lrow;
            uint32_t bh0, bh1, bh2, bh3, bl0, bl1, bl2, bl3;
            ldsm4(bh0, bh1, bh2, bh3, s2u(BH + nrow * SA + kk));
            ldsm4(bl0, bl1, bl2, bl3, s2u(BL + nrow * SA + kk));
            mmabf(acc[2 * np], ah0, ah1, ah2, ah3, bh0, bh2);
            mmabf(acc[2 * np], ah0, ah1, ah2, ah3, bl0, bl2);
            mmabf(acc[2 * np], al0, al1, al2, al3, bh0, bh2);
            mmabf(acc[2 * np + 1], ah0, ah1, ah2, ah3, bh1, bh3);
            mmabf(acc[2 * np + 1], ah0, ah1, ah2, ah3, bl1, bl3);
            mmabf(acc[2 * np + 1], al0, al1, al2, al3, bh1, bh3);
        }
    }

    const float* bias = B1g + l * F2;
    int r = lane >> 2, cp = (lane & 3) * 2;
#pragma unroll
    for (int nt = 0; nt < 4; nt++) {
        int col = ncol0 + wn * 32 + nt * 8 + cp;
        float b0 = __ldg(bias + col), b1 = __ldg(bias + col + 1);
#pragma unroll
        for (int half = 0; half < 2; half++) {
            int row = row0 + wm * 16 + r + half * 8;
            if (row < NV) {
                float v0 = fmaxf(acc[nt][2 * half + 0] + b0, 0.f);
                float v1 = fmaxf(acc[nt][2 * half + 1] + b1, 0.f);
                __nv_bfloat16 h0, l0, h1, l1;
                splitbf(v0, h0, l0);
                splitbf(v1, h1, l1);
                uint32_t hw = (uint32_t)__bfloat16_as_ushort(h0) |
                              ((uint32_t)__bfloat16_as_ushort(h1) << 16);
                uint32_t lw = (uint32_t)__bfloat16_as_ushort(l0) |
                              ((uint32_t)__bfloat16_as_ushort(l1) << 16);
                *(uint32_t*)(MidHi + (size_t)row * F2 + col) = hw;
                *(uint32_t*)(MidLo + (size_t)row * F2 + col) = lw;
            }
        }
    }
}

__global__ void __launch_bounds__(256) g2(const float* __restrict__ B2g, int l) {
    const int SA = 136;
    __nv_bfloat16* AH = (__nv_bfloat16*)dsm;
    __nv_bfloat16* AL = AH + 64 * SA;
    __nv_bfloat16* BH = AL + 64 * SA;
    __nv_bfloat16* BL = BH + 128 * SA;
    int tid = threadIdx.x;
    int row0 = blockIdx.x * 64;
    int lane = tid & 31, wid = tid >> 5;
    int wm = wid & 1, wn = wid >> 1;
    int lrow = lane & 15, lkof = (lane >> 4) * 8;

    float acc[2][4][4];
#pragma unroll
    for (int a = 0; a < 2; a++)
#pragma unroll
        for (int i = 0; i < 4; i++)
#pragma unroll
            for (int j = 0; j < 4; j++) acc[a][i][j] = 0.f;

    for (int pass = 0; pass < 2; pass++) {
        if (pass) __syncthreads();
        {
            const uint32_t* MH = (const uint32_t*)MidHi;
            const uint32_t* ML = (const uint32_t*)MidLo;
            uint32_t* AH32 = (uint32_t*)AH;
            uint32_t* AL32 = (uint32_t*)AL;
            for (int idx = tid; idx < 64 * 64; idx += 256) {
                int m = idx >> 6, k2 = idx & 63;
                int row = row0 + m;
                uint32_t h = 0, lo = 0;
                if (row < NV) {
                    h = MH[(size_t)row * 128 + pass * 64 + k2];
                    lo = ML[(size_t)row * 128 + pass * 64 + k2];
                }
                AH32[m * 68 + k2] = h;
                AL32[m * 68 + k2] = lo;
            }
        }
        {
            const uint32_t* WH = (const uint32_t*)W2Ht + (size_t)l * F * 128;
            const uint32_t* WL = (const uint32_t*)W2Lt + (size_t)l * F * 128;
            uint32_t* BH32 = (uint32_t*)BH;
            uint32_t* BL32 = (uint32_t*)BL;
            for (int idx = tid; idx < 128 * 64; idx += 256) {
                int n = idx >> 6, k2 = idx & 63;
                BH32[n * 68 + k2] = WH[n * 128 + pass * 64 + k2];
                BL32[n * 68 + k2] = WL[n * 128 + pass * 64 + k2];
            }
        }
        __syncthreads();

#pragma unroll
        for (int ks = 0; ks < 8; ks++) {
            int kk = ks * 16 + lkof;
#pragma unroll
            for (int mt = 0; mt < 2; mt++) {
                uint32_t ah0, ah1, ah2, ah3, al0, al1, al2, al3;
                ldsm4(ah0, ah1, ah2, ah3,
                      s2u(AH + (wm * 32 + mt * 16 + lrow) * SA + kk));
                ldsm4(al0, al1, al2, al3,
                      s2u(AL + (wm * 32 + mt * 16 + lrow) * SA + kk));
#pragma unroll
                for (int np = 0; np < 2; np++) {
                    int nrow = wn * 32 + np * 16 + lrow;
                    uint32_t bh0, bh1, bh2, bh3, bl0, bl1, bl2, bl3;
                    ldsm4(bh0, bh1, bh2, bh3, s2u(BH + nrow * SA + kk));
                    ldsm4(bl0, bl1, bl2, bl3, s2u(BL + nrow * SA + kk));
                    mmabf(acc[mt][2 * np], ah0, ah1, ah2, ah3, bh0, bh2);
                    mmabf(acc[mt][2 * np], ah0, ah1, ah2, ah3, bl0, bl2);
                    mmabf(acc[mt][2 * np], al0, al1, al2, al3, bh0, bh2);
                    mmabf(acc[mt][2 * np + 1], ah0, ah1, ah2, ah3, bh1, bh3);
                    mmabf(acc[mt][2 * np + 1], ah0, ah1, ah2, ah3, bl1, bl3);
                    mmabf(acc[mt][2 * np + 1], al0, al1, al2, al3, bh1, bh3);
                }
            }
        }
    }

    const float* bias = B2g + l * F;
    int r = lane >> 2, cp = (lane & 3) * 2;
#pragma unroll
    for (int mt = 0; mt < 2; mt++) {
#pragma unroll
        for (int nt = 0; nt < 4; nt++) {
            int col = wn * 32 + nt * 8 + cp;
            float b0 = __ldg(bias + col), b1 = __ldg(bias + col + 1);
#pragma unroll
            for (int half = 0; half < 2; half++) {
                int row = row0 + wm * 32 + mt * 16 + r + half * 8;
                if (row < NV) {
                    float2 o;
                    o.x = acc[mt][nt][2 * half + 0] + b0;
                    o.y = acc[mt][nt][2 * half + 1] + b1;
                    *(float2*)(Obuf + (size_t)row * F + col) = o;
                }
            }
        }
    }
}

// ================= launch =================
extern "C" void kernel_launch(void* const* d_in, const int* in_sizes, int n_in,
                              void* d_out, int out_size) {
    const int*   X   = (const int*)d_in[0];
    const int*   EI  = (const int*)d_in[1];
    const int*   EA  = (const int*)d_in[2];
    const float* XE1 = (const float*)d_in[3];
    const float* XE2 = (const float*)d_in[4];
    const float* EE1 = (const float*)d_in[5];
    const float* EE2 = (const float*)d_in[6];
    const float* W1g = (const float*)d_in[7];
    const float* B1g = (const float*)d_in[8];
    const float* W2g = (const float*)d_in[9];
    const float* B2g = (const float*)d_in[10];
    const float* EPS = (const float*)d_in[11];
    const float* G   = (const float*)d_in[12];
    const float* B   = (const float*)d_in[13];
    float* dout = (float*)d_out;

    const int SM1 = (32 * 136 * 2 + 128 * 136 * 2) * 2;  // 87040 B
    const int SM2 = (64 * 136 * 2 + 128 * 136 * 2) * 2;  // 104448 B
    cudaFuncSetAttribute(g1, cudaFuncAttributeMaxDynamicSharedMemorySize, SM1);
    cudaFuncSetAttribute(g2, cudaFuncAttributeMaxDynamicSharedMemorySize, SM2);

    long long nvf = (long long)NV * F;
    int gb_n = (int)((nvf + 255) / 256);

    // prep: weights, h0, CSR
    w_prep<<<(NL * F * F2 + 255) / 256, 256>>>(W1g, W2g);
    c_init<<<gb_n, 256>>>(X, XE1, XE2);
    z_zero<<<(NV + 255) / 256, 256>>>();
    z_count<<<(NE + 255) / 256, 256>>>(EI);
    int nb = (NV + 1023) / 1024;  // 98
    z_scan1<<<nb, 1024>>>();
    z_scan2<<<1, 128>>>(nb);
    z_scan3<<<(NV + 255) / 256, 256>>>();
    z_scatter<<<(NE + 255) / 256, 256>>>(EI, EA);

    dim3 grid1((NV + 31) / 32, 2);
    int grid2 = (NV + 63) / 64;
    int gagg = (NV + 7) / 8;  // 12500
    for (int l = 0; l < NL; l++) {
        k_agg<<<gagg, 256>>>(EE1, EE2, EPS, l);
        g1<<<grid1, 256, SM1>>>(B1g, l);
        g2<<<grid2, 256, SM2>>>(B2g, l);
        c_stats<<<F, 256>>>();
        c_fin<<<1, F>>>(G, B, l);
        c_apply<<<gb_n, 256>>>(dout, (l == NL - 1) ? 1 : 0);
    }
}

// round 14
// speedup vs baseline: 2.3399x; 1.0896x over previous
#include <cuda_runtime.h>
#include <cuda_bf16.h>
#include <stdint.h>

#define NV 100000
#define NE 600000
#define F 128
#define F2 256
#define NL 5

// ---------------- scratch ----------------
__device__ float Hbuf[NV * F];        // aggregate output (GEMM1 input)
__device__ float Obuf[NV * F];        // GEMM2 output (pre-BN h)
__device__ __nv_bfloat16 MidHi[(size_t)NV * F2];
__device__ __nv_bfloat16 MidLo[(size_t)NV * F2];
__device__ float Sum_[F];
__device__ float Sq_[F];
__device__ float Scale_[F];
__device__ float Shift_[F];
__device__ __nv_bfloat16 W1Ht[NL * F2 * F];
__device__ __nv_bfloat16 W1Lt[NL * F2 * F];
__device__ __nv_bfloat16 W2Ht[NL * F * F2];
__device__ __nv_bfloat16 W2Lt[NL * F * F2];
// CSR by destination
__device__ int g_cnt[NV];
__device__ int g_cursor[NV];
__device__ int g_rowptr[NV + 1];
__device__ int g_bsum[128];
__device__ int g_boff[128];
__device__ int g_elist[NE];   // src | code<<20

__device__ __forceinline__ void splitbf(float v, __nv_bfloat16& h, __nv_bfloat16& lo) {
    h = __float2bfloat16(v);
    lo = __float2bfloat16(v - __bfloat162float(h));
}

// ================= init / CSR build =================
__global__ void c_init(const int* X, const float* XE1, const float* XE2) {
    long long idx = (long long)blockIdx.x * blockDim.x + threadIdx.x;
    if (idx >= (long long)NV * F) return;
    int v = (int)(idx / F);
    int f = (int)(idx % F);
    int atom = X[2 * v];
    if (atom < 0) atom = 0;
    if (atom > 118) atom = 118;
    int chir = X[2 * v + 1];
    if (chir < 0) chir = 0;
    if (chir > 2) chir = 2;
    Obuf[idx] = XE1[atom * F + f] + XE2[chir * F + f];  // h0 (pre-BN buffer)
}

__global__ void z_init_bn() {
    int f = threadIdx.x;  // 128
    Sum_[f] = 0.f;
    Sq_[f] = 0.f;
    Scale_[f] = 1.f;
    Shift_[f] = 0.f;
}

__global__ void z_zero() {
    int i = blockIdx.x * blockDim.x + threadIdx.x;
    if (i < NV) g_cnt[i] = 0;
}

__global__ void z_count(const int* EI) {
    int e = blockIdx.x * blockDim.x + threadIdx.x;
    if (e >= NE) return;
    int d = EI[NE + e];
    if (d < 0) d = 0;
    if (d >= NV) d = NV - 1;
    atomicAdd(&g_cnt[d], 1);
}

__global__ void z_scan1() {
    __shared__ int s[1024];
    int t = threadIdx.x;
    int gi = blockIdx.x * 1024 + t;
    int v = (gi < NV) ? g_cnt[gi] : 0;
    s[t] = v;
    __syncthreads();
    for (int off = 1; off < 1024; off <<= 1) {
        int xv = 0;
        if (t >= off) xv = s[t - off];
        __syncthreads();
        s[t] += xv;
        __syncthreads();
    }
    if (gi < NV) g_cursor[gi] = s[t] - v;
    if (t == 1023) g_bsum[blockIdx.x] = s[t];
}

__global__ void z_scan2(int nb) {
    __shared__ int s[128];
    int t = threadIdx.x;
    int v = (t < nb) ? g_bsum[t] : 0;
    s[t] = v;
    __syncthreads();
    for (int off = 1; off < 128; off <<= 1) {
        int xv = 0;
        if (t >= off) xv = s[t - off];
        __syncthreads();
        s[t] += xv;
        __syncthreads();
    }
    g_boff[t] = s[t] - v;
    if (t == 0) g_rowptr[NV] = NE;
}

__global__ void z_scan3() {
    int i = blockIdx.x * blockDim.x + threadIdx.x;
    if (i >= NV) return;
    int rp = g_cursor[i] + g_boff[i >> 10];
    g_rowptr[i] = rp;
    g_cursor[i] = rp;
}

__global__ void z_scatter(const int* EI, const int* EA) {
    int e = blockIdx.x * blockDim.x + threadIdx.x;
    if (e >= NE) return;
    int d = EI[NE + e];
    if (d < 0) d = 0;
    if (d >= NV) d = NV - 1;
    int pos = atomicAdd(&g_cursor[d], 1);
    if (pos < 0) pos = 0;
    if (pos >= NE) pos = NE - 1;
    int s = EI[e];
    if (s < 0) s = 0;
    if (s >= NV) s = NV - 1;
    int b = EA[2 * e];
    if (b < 0) b = 0;
    if (b > 4) b = 4;
    int dr = EA[2 * e + 1];
    if (dr < 0) dr = 0;
    if (dr > 2) dr = 2;
    g_elist[pos] = s | ((b * 3 + dr) << 20);
}

// ================= aggregation with inline BN =================
// h(x) = maybe_relu(Obuf[x]*Scale+Shift); Hbuf[v] = (1+eps)h(v) + relu(h(v)+e0)
//        + sum_in-edges relu(h(src)+e(code))
__global__ void __launch_bounds__(256) k_agg(const float* __restrict__ EE1,
                                             const float* __restrict__ EE2,
                                             const float* __restrict__ EPS,
                                             int l, int dorelu) {
    __shared__ __align__(16) float etab[15 * F];
    int t = threadIdx.x;
    for (int j = t; j < 15 * F; j += 256) {
        int c = j >> 7, f = j & 127;
        etab[j] = EE1[(l * 5 + c / 3) * F + f] + EE2[(l * 3 + c % 3) * F + f];
    }
    __syncthreads();
    int gw = blockIdx.x * 8 + (t >> 5);
    int lane = t & 31;
    if (gw >= NV) return;
    float ep1 = 1.0f + EPS[l];
    const float4* Gv = (const float4*)Obuf;
    const float4* et = (const float4*)etab;
    float4 sc = ((const float4*)Scale_)[lane];
    float4 sh = ((const float4*)Shift_)[lane];

    // self
    float4 g = Gv[(size_t)gw * 32 + lane];
    float4 hn;
    hn.x = fmaf(g.x, sc.x, sh.x);
    hn.y = fmaf(g.y, sc.y, sh.y);
    hn.z = fmaf(g.z, sc.z, sh.z);
    hn.w = fmaf(g.w, sc.w, sh.w);
    if (dorelu) {
        hn.x = fmaxf(hn.x, 0.f); hn.y = fmaxf(hn.y, 0.f);
        hn.z = fmaxf(hn.z, 0.f); hn.w = fmaxf(hn.w, 0.f);
    }
    float4 e0 = et[lane];
    float4 acc;
    acc.x = ep1 * hn.x + fmaxf(hn.x + e0.x, 0.f);
    acc.y = ep1 * hn.y + fmaxf(hn.y + e0.y, 0.f);
    acc.z = ep1 * hn.z + fmaxf(hn.z + e0.z, 0.f);
    acc.w = ep1 * hn.w + fmaxf(hn.w + e0.w, 0.f);

    int beg = g_rowptr[gw];
    int end = g_rowptr[gw + 1];
    if (beg < 0) beg = 0;
    if (end > NE) end = NE;
    for (int base = beg; base < end; base += 32) {
        int n = end - base;
        if (n > 32) n = 32;
        int p = 0;
        if (lane < n) p = g_elist[base + lane];
        for (int j = 0; j < n; j++) {
            int pj = __shfl_sync(0xFFFFFFFF, p, j);
            int src = pj & 0xFFFFF;
            int code = (pj >> 20) & 15;
            if (src >= NV) src = NV - 1;
            if (code > 14) code = 14;
            float4 gs = __ldg(&Gv[(size_t)src * 32 + lane]);
            float4 hs;
            hs.x = fmaf(gs.x, sc.x, sh.x);
            hs.y = fmaf(gs.y, sc.y, sh.y);
            hs.z = fmaf(gs.z, sc.z, sh.z);
            hs.w = fmaf(gs.w, sc.w, sh.w);
            if (dorelu) {
                hs.x = fmaxf(hs.x, 0.f); hs.y = fmaxf(hs.y, 0.f);
                hs.z = fmaxf(hs.z, 0.f); hs.w = fmaxf(hs.w, 0.f);
            }
            float4 ev = et[code * 32 + lane];
            acc.x += fmaxf(hs.x + ev.x, 0.f);
            acc.y += fmaxf(hs.y + ev.y, 0.f);
            acc.z += fmaxf(hs.z + ev.z, 0.f);
            acc.w += fmaxf(hs.w + ev.w, 0.f);
        }
    }
    ((float4*)Hbuf)[(size_t)gw * 32 + lane] = acc;
}

// ================= BN finalize (also re-zeros accumulators) =================
__global__ void c_fin(const float* G, const float* B, int l) {
    int f = threadIdx.x;
    float mean = Sum_[f] / (float)NV;
    float var = Sq_[f] / (float)NV - mean * mean;
    if (var < 0.f) var = 0.f;
    float rstd = rsqrtf(var + 1e-5f);
    float sc = rstd * G[l * F + f];
    Scale_[f] = sc;
    Shift_[f] = B[l * F + f] - mean * sc;
    Sum_[f] = 0.f;
    Sq_[f] = 0.f;
}

__global__ void c_apply_last(float* dout) {
    long long idx = (long long)blockIdx.x * blockDim.x + threadIdx.x;
    if (idx >= (long long)NV * F) return;
    int f = (int)(idx % F);
    dout[idx] = Obuf[idx] * Scale_[f] + Shift_[f];
}

// ================= weight pre-split =================
__global__ void w_prep(const float* W1g, const float* W2g) {
    int idx = blockIdx.x * blockDim.x + threadIdx.x;
    if (idx < NL * F * F2) {
        int l = idx / (F * F2);
        int rem = idx % (F * F2);
        int k = rem / F2, n = rem % F2;
        __nv_bfloat16 h, lo;
        splitbf(W1g[idx], h, lo);
        W1Ht[((size_t)l * F2 + n) * F + k] = h;
        W1Lt[((size_t)l * F2 + n) * F + k] = lo;
        int k2 = rem / F, n2 = rem % F;
        splitbf(W2g[idx], h, lo);
        W2Ht[((size_t)l * F + n2) * F2 + k2] = h;
        W2Lt[((size_t)l * F + n2) * F2 + k2] = lo;
    }
}

// ================= mma.sync split-bf16 GEMM =================
__device__ __forceinline__ uint32_t s2u(const void* p) {
    return (uint32_t)__cvta_generic_to_shared(p);
}

__device__ __forceinline__ void ldsm4(uint32_t& r0, uint32_t& r1, uint32_t& r2,
                                      uint32_t& r3, uint32_t a) {
    asm volatile("ldmatrix.sync.aligned.m8n8.x4.shared.b16 {%0,%1,%2,%3}, [%4];"
                 : "=r"(r0), "=r"(r1), "=r"(r2), "=r"(r3) : "r"(a));
}

__device__ __forceinline__ void mmabf(float* c,
                                      uint32_t a0, uint32_t a1, uint32_t a2, uint32_t a3,
                                      uint32_t b0, uint32_t b1) {
    asm volatile(
        "mma.sync.aligned.m16n8k16.row.col.f32.bf16.bf16.f32 "
        "{%0,%1,%2,%3},{%4,%5,%6,%7},{%8,%9},{%0,%1,%2,%3};"
        : "+f"(c[0]), "+f"(c[1]), "+f"(c[2]), "+f"(c[3])
        : "r"(a0), "r"(a1), "r"(a2), "r"(a3), "r"(b0), "r"(b1));
}

extern __shared__ __align__(16) char dsm[];

// ---- GEMM1: Mid = split(relu(Hbuf @ W1 + b1)). CTA: M=32, N=128 ----
__global__ void __launch_bounds__(256) g1(const float* __restrict__ B1g, int l) {
    const int SA = 136;
    __nv_bfloat16* AH = (__nv_bfloat16*)dsm;
    __nv_bfloat16* AL = AH + 32 * SA;
    __nv_bfloat16* BH = AL + 32 * SA;
    __nv_bfloat16* BL = BH + 128 * SA;
    int tid = threadIdx.x;
    int row0 = blockIdx.x * 32;
    int ncol0 = blockIdx.y * 128;

    for (int idx = tid; idx < 32 * 128; idx += 256) {
        int m = idx >> 7, k = idx & 127;
        int row = row0 + m;
        float v = (row < NV) ? Hbuf[(size_t)row * F + k] : 0.f;
        __nv_bfloat16 h, lo;
        splitbf(v, h, lo);
        AH[m * SA + k] = h;
        AL[m * SA + k] = lo;
    }
    {
        const uint32_t* WH = (const uint32_t*)W1Ht + ((size_t)l * F2 + ncol0) * 64;
        const uint32_t* WL = (const uint32_t*)W1Lt + ((size_t)l * F2 + ncol0) * 64;
        uint32_t* BH32 = (uint32_t*)BH;
        uint32_t* BL32 = (uint32_t*)BL;
        for (int idx = tid; idx < 128 * 64; idx += 256) {
            int n = idx >> 6, k2 = idx & 63;
            BH32[n * 68 + k2] = WH[n * 64 + k2];
            BL32[n * 68 + k2] = WL[n * 64 + k2];
        }
    }
    __syncthreads();

    int lane = tid & 31, wid = tid >> 5;
    int wm = wid & 1, wn = wid >> 1;
    float acc[4][4];
#pragma unroll
    for (int i = 0; i < 4; i++)
#pragma unroll
        for (int j = 0; j < 4; j++) acc[i][j] = 0.f;

    int lrow = lane & 15, lkof = (lane >> 4) * 8;

#pragma unroll
    for (int ks = 0; ks < 8; ks++) {
        int kk = ks * 16 + lkof;
        uint32_t ah0, ah1, ah2, ah3, al0, al1, al2, al3;
        ldsm4(ah0, ah1, ah2, ah3, s2u(AH + (wm * 16 + lrow) * SA + kk));
        ldsm4(al0, al1, al2, al3, s2u(AL + (wm * 16 + lrow) * SA + kk));
#pragma unroll
        for (int np = 0; np < 2; np++) {
            int nrow = wn * 32 + np * 16 + lrow;
            uint32_t bh0, bh1, bh2, bh3, bl0, bl1, bl2, bl3;
            ldsm4(bh0, bh1, bh2, bh3, s2u(BH + nrow * SA + kk));
            ldsm4(bl0, bl1, bl2, bl3, s2u(BL + nrow * SA + kk));
            mmabf(acc[2 * np], ah0, ah1, ah2, ah3, bh0, bh2);
            mmabf(acc[2 * np], ah0, ah1, ah2, ah3, bl0, bl2);
            mmabf(acc[2 * np], al0, al1, al2, al3, bh0, bh2);
            mmabf(acc[2 * np + 1], ah0, ah1, ah2, ah3, bh1, bh3);
            mmabf(acc[2 * np + 1], ah0, ah1, ah2, ah3, bl1, bl3);
            mmabf(acc[2 * np + 1], al0, al1, al2, al3, bh1, bh3);
        }
    }

    const float* bias = B1g + l * F2;
    int r = lane >> 2, cp = (lane & 3) * 2;
#pragma unroll
    for (int nt = 0; nt < 4; nt++) {
        int col = ncol0 + wn * 32 + nt * 8 + cp;
        float b0 = __ldg(bias + col), b1 = __ldg(bias + col + 1);
#pragma unroll
        for (int half = 0; half < 2; half++) {
            int row = row0 + wm * 16 + r + half * 8;
            if (row < NV) {
                float v0 = fmaxf(acc[nt][2 * half + 0] + b0, 0.f);
                float v1 = fmaxf(acc[nt][2 * half + 1] + b1, 0.f);
                __nv_bfloat16 h0, l0, h1, l1;
                splitbf(v0, h0, l0);
                splitbf(v1, h1, l1);
                uint32_t hw = (uint32_t)__bfloat16_as_ushort(h0) |
                              ((uint32_t)__bfloat16_as_ushort(h1) << 16);
                uint32_t lw = (uint32_t)__bfloat16_as_ushort(l0) |
                              ((uint32_t)__bfloat16_as_ushort(l1) << 16);
                *(uint32_t*)(MidHi + (size_t)row * F2 + col) = hw;
                *(uint32_t*)(MidLo + (size_t)row * F2 + col) = lw;
            }
        }
    }
}

// ---- GEMM2: Obuf = Mid @ W2 + b2 (+ fused BN stats) ----
__global__ void __launch_bounds__(256) g2(const float* __restrict__ B2g, int l) {
    const int SA = 136;
    __nv_bfloat16* AH = (__nv_bfloat16*)dsm;
    __nv_bfloat16* AL = AH + 64 * SA;
    __nv_bfloat16* BH = AL + 64 * SA;
    __nv_bfloat16* BL = BH + 128 * SA;
    int tid = threadIdx.x;
    int row0 = blockIdx.x * 64;
    int lane = tid & 31, wid = tid >> 5;
    int wm = wid & 1, wn = wid >> 1;
    int lrow = lane & 15, lkof = (lane >> 4) * 8;

    float acc[2][4][4];
#pragma unroll
    for (int a = 0; a < 2; a++)
#pragma unroll
        for (int i = 0; i < 4; i++)
#pragma unroll
            for (int j = 0; j < 4; j++) acc[a][i][j] = 0.f;

    for (int pass = 0; pass < 2; pass++) {
        if (pass) __syncthreads();
        {
            const uint32_t* MH = (const uint32_t*)MidHi;
            const uint32_t* ML = (const uint32_t*)MidLo;
            uint32_t* AH32 = (uint32_t*)AH;
            uint32_t* AL32 = (uint32_t*)AL;
            for (int idx = tid; idx < 64 * 64; idx += 256) {
                int m = idx >> 6, k2 = idx & 63;
                int row = row0 + m;
                uint32_t h = 0, lo = 0;
                if (row < NV) {
                    h = MH[(size_t)row * 128 + pass * 64 + k2];
                    lo = ML[(size_t)row * 128 + pass * 64 + k2];
                }
                AH32[m * 68 + k2] = h;
                AL32[m * 68 + k2] = lo;
            }
        }
        {
            const uint32_t* WH = (const uint32_t*)W2Ht + (size_t)l * F * 128;
            const uint32_t* WL = (const uint32_t*)W2Lt + (size_t)l * F * 128;
            uint32_t* BH32 = (uint32_t*)BH;
            uint32_t* BL32 = (uint32_t*)BL;
            for (int idx = tid; idx < 128 * 64; idx += 256) {
                int n = idx >> 6, k2 = idx & 63;
                BH32[n * 68 + k2] = WH[n * 128 + pass * 64 + k2];
                BL32[n * 68 + k2] = WL[n * 128 + pass * 64 + k2];
            }
        }
        __syncthreads();

#pragma unroll
        for (int ks = 0; ks < 8; ks++) {
            int kk = ks * 16 + lkof;
#pragma unroll
            for (int mt = 0; mt < 2; mt++) {
                uint32_t ah0, ah1, ah2, ah3, al0, al1, al2, al3;
                ldsm4(ah0, ah1, ah2, ah3,
                      s2u(AH + (wm * 32 + mt * 16 + lrow) * SA + kk));
                ldsm4(al0, al1, al2, al3,
                      s2u(AL + (wm * 32 + mt * 16 + lrow) * SA + kk));
#pragma unroll
                for (int np = 0; np < 2; np++) {
                    int nrow = wn * 32 + np * 16 + lrow;
                    uint32_t bh0, bh1, bh2, bh3, bl0, bl1, bl2, bl3;
                    ldsm4(bh0, bh1, bh2, bh3, s2u(BH + nrow * SA + kk));
                    ldsm4(bl0, bl1, bl2, bl3, s2u(BL + nrow * SA + kk));
                    mmabf(acc[mt][2 * np], ah0, ah1, ah2, ah3, bh0, bh2);
                    mmabf(acc[mt][2 * np], ah0, ah1, ah2, ah3, bl0, bl2);
                    mmabf(acc[mt][2 * np], al0, al1, al2, al3, bh0, bh2);
                    mmabf(acc[mt][2 * np + 1], ah0, ah1, ah2, ah3, bh1, bh3);
                    mmabf(acc[mt][2 * np + 1], ah0, ah1, ah2, ah3, bl1, bl3);
                    mmabf(acc[mt][2 * np + 1], al0, al1, al2, al3, bh1, bh3);
                }
            }
        }
    }

    const float* bias = B2g + l * F;
    int r = lane >> 2, cp = (lane & 3) * 2;
    float lsum[4][2], lsq[4][2];
#pragma unroll
    for (int nt = 0; nt < 4; nt++) {
        lsum[nt][0] = 0.f; lsum[nt][1] = 0.f;
        lsq[nt][0] = 0.f; lsq[nt][1] = 0.f;
    }
#pragma unroll
    for (int mt = 0; mt < 2; mt++) {
#pragma unroll
        for (int nt = 0; nt < 4; nt++) {
            int col = wn * 32 + nt * 8 + cp;
            float b0 = __ldg(bias + col), b1 = __ldg(bias + col + 1);
#pragma unroll
            for (int half = 0; half < 2; half++) {
                int row = row0 + wm * 32 + mt * 16 + r + half * 8;
                if (row < NV) {
                    float2 o;
                    o.x = acc[mt][nt][2 * half + 0] + b0;
                    o.y = acc[mt][nt][2 * half + 1] + b1;
                    *(float2*)(Obuf + (size_t)row * F + col) = o;
                    lsum[nt][0] += o.x; lsum[nt][1] += o.y;
                    lsq[nt][0] += o.x * o.x; lsq[nt][1] += o.y * o.y;
                }
            }
        }
    }
    // reduce over the 8 row-lanes (lane bits [4:2]) and atomically accumulate
#pragma unroll
    for (int nt = 0; nt < 4; nt++) {
#pragma unroll
        for (int c = 0; c < 2; c++) {
#pragma unroll
            for (int off = 4; off < 32; off <<= 1) {
                lsum[nt][c] += __shfl_xor_sync(0xFFFFFFFF, lsum[nt][c], off);
                lsq[nt][c] += __shfl_xor_sync(0xFFFFFFFF, lsq[nt][c], off);
            }
        }
    }
    if (lane < 4) {
#pragma unroll
        for (int nt = 0; nt < 4; nt++) {
            int col = wn * 32 + nt * 8 + lane * 2;
            atomicAdd(&Sum_[col], lsum[nt][0]);
            atomicAdd(&Sum_[col + 1], lsum[nt][1]);
            atomicAdd(&Sq_[col], lsq[nt][0]);
            atomicAdd(&Sq_[col + 1], lsq[nt][1]);
        }
    }
}

// ================= launch =================
extern "C" void kernel_launch(void* const* d_in, const int* in_sizes, int n_in,
                              void* d_out, int out_size) {
    const int*   X   = (const int*)d_in[0];
    const int*   EI  = (const int*)d_in[1];
    const int*   EA  = (const int*)d_in[2];
    const float* XE1 = (const float*)d_in[3];
    const float* XE2 = (const float*)d_in[4];
    const float* EE1 = (const float*)d_in[5];
    const float* EE2 = (const float*)d_in[6];
    const float* W1g = (const float*)d_in[7];
    const float* B1g = (const float*)d_in[8];
    const float* W2g = (const float*)d_in[9];
    const float* B2g = (const float*)d_in[10];
    const float* EPS = (const float*)d_in[11];
    const float* G   = (const float*)d_in[12];
    const float* B   = (const float*)d_in[13];
    float* dout = (float*)d_out;

    const int SM1 = (32 * 136 * 2 + 128 * 136 * 2) * 2;  // 87040 B
    const int SM2 = (64 * 136 * 2 + 128 * 136 * 2) * 2;  // 104448 B
    cudaFuncSetAttribute(g1, cudaFuncAttributeMaxDynamicSharedMemorySize, SM1);
    cudaFuncSetAttribute(g2, cudaFuncAttributeMaxDynamicSharedMemorySize, SM2);

    long long nvf = (long long)NV * F;
    int gb_n = (int)((nvf + 255) / 256);

    // prep: weights, h0, BN identity, CSR
    w_prep<<<(NL * F * F2 + 255) / 256, 256>>>(W1g, W2g);
    c_init<<<gb_n, 256>>>(X, XE1, XE2);
    z_init_bn<<<1, 128>>>();
    z_zero<<<(NV + 255) / 256, 256>>>();
    z_count<<<(NE + 255) / 256, 256>>>(EI);
    int nb = (NV + 1023) / 1024;  // 98
    z_scan1<<<nb, 1024>>>();
    z_scan2<<<1, 128>>>(nb);
    z_scan3<<<(NV + 255) / 256, 256>>>();
    z_scatter<<<(NE + 255) / 256, 256>>>(EI, EA);

    dim3 grid1((NV + 31) / 32, 2);
    int grid2 = (NV + 63) / 64;
    int gagg = (NV + 7) / 8;  // 12500
    for (int l = 0; l < NL; l++) {
        k_agg<<<gagg, 256>>>(EE1, EE2, EPS, l, l > 0 ? 1 : 0);
        g1<<<grid1, 256, SM1>>>(B1g, l);
        g2<<<grid2, 256, SM2>>>(B2g, l);
        c_fin<<<1, 128>>>(G, B, l);
    }
    c_apply_last<<<gb_n, 256>>>(dout);
}

// round 15
// speedup vs baseline: 2.8135x; 1.2024x over previous
#include <cuda_runtime.h>
#include <cuda_bf16.h>
#include <stdint.h>

#define NV 100000
#define NE 600000
#define F 128
#define F2 256
#define NL 5

// ---------------- scratch ----------------
__device__ float Obuf[NV * F];                    // GEMM2 output (pre-BN h)
__device__ __nv_bfloat16 AggHi[(size_t)NV * F];   // aggregate, split bf16
__device__ __nv_bfloat16 AggLo[(size_t)NV * F];
__device__ __nv_bfloat16 MidHi[(size_t)NV * F2];
__device__ __nv_bfloat16 MidLo[(size_t)NV * F2];
__device__ float Sum_[F];
__device__ float Sq_[F];
__device__ float Scale_[F];
__device__ float Shift_[F];
__device__ __nv_bfloat16 W1Ht[NL * F2 * F];
__device__ __nv_bfloat16 W1Lt[NL * F2 * F];
__device__ __nv_bfloat16 W2Ht[NL * F * F2];
__device__ __nv_bfloat16 W2Lt[NL * F * F2];
// CSR by destination
__device__ int g_cnt[NV];
__device__ int g_cursor[NV];
__device__ int g_rowptr[NV + 1];
__device__ int g_bsum[128];
__device__ int g_boff[128];
__device__ int g_elist[NE];   // src | code<<20

__device__ __forceinline__ void splitbf(float v, __nv_bfloat16& h, __nv_bfloat16& lo) {
    h = __float2bfloat16(v);
    lo = __float2bfloat16(v - __bfloat162float(h));
}

__device__ __forceinline__ uint32_t pack2(float v0, float v1,
                                          uint32_t& lo_out) {
    __nv_bfloat16 h0, l0, h1, l1;
    splitbf(v0, h0, l0);
    splitbf(v1, h1, l1);
    lo_out = (uint32_t)__bfloat16_as_ushort(l0) |
             ((uint32_t)__bfloat16_as_ushort(l1) << 16);
    return (uint32_t)__bfloat16_as_ushort(h0) |
           ((uint32_t)__bfloat16_as_ushort(h1) << 16);
}

// ================= init / CSR build =================
__global__ void c_init(const int* X, const float* XE1, const float* XE2) {
    long long idx = (long long)blockIdx.x * blockDim.x + threadIdx.x;
    if (idx >= (long long)NV * F) return;
    int v = (int)(idx / F);
    int f = (int)(idx % F);
    int atom = X[2 * v];
    if (atom < 0) atom = 0;
    if (atom > 118) atom = 118;
    int chir = X[2 * v + 1];
    if (chir < 0) chir = 0;
    if (chir > 2) chir = 2;
    Obuf[idx] = XE1[atom * F + f] + XE2[chir * F + f];  // h0 (pre-BN buffer)
}

__global__ void z_init_bn() {
    int f = threadIdx.x;  // 128
    Sum_[f] = 0.f;
    Sq_[f] = 0.f;
    Scale_[f] = 1.f;
    Shift_[f] = 0.f;
}

__global__ void z_zero() {
    int i = blockIdx.x * blockDim.x + threadIdx.x;
    if (i < NV) g_cnt[i] = 0;
}

__global__ void z_count(const int* EI) {
    int e = blockIdx.x * blockDim.x + threadIdx.x;
    if (e >= NE) return;
    int d = EI[NE + e];
    if (d < 0) d = 0;
    if (d >= NV) d = NV - 1;
    atomicAdd(&g_cnt[d], 1);
}

__global__ void z_scan1() {
    __shared__ int s[1024];
    int t = threadIdx.x;
    int gi = blockIdx.x * 1024 + t;
    int v = (gi < NV) ? g_cnt[gi] : 0;
    s[t] = v;
    __syncthreads();
    for (int off = 1; off < 1024; off <<= 1) {
        int xv = 0;
        if (t >= off) xv = s[t - off];
        __syncthreads();
        s[t] += xv;
        __syncthreads();
    }
    if (gi < NV) g_cursor[gi] = s[t] - v;
    if (t == 1023) g_bsum[blockIdx.x] = s[t];
}

__global__ void z_scan2(int nb) {
    __shared__ int s[128];
    int t = threadIdx.x;
    int v = (t < nb) ? g_bsum[t] : 0;
    s[t] = v;
    __syncthreads();
    for (int off = 1; off < 128; off <<= 1) {
        int xv = 0;
        if (t >= off) xv = s[t - off];
        __syncthreads();
        s[t] += xv;
        __syncthreads();
    }
    g_boff[t] = s[t] - v;
    if (t == 0) g_rowptr[NV] = NE;
}

__global__ void z_scan3() {
    int i = blockIdx.x * blockDim.x + threadIdx.x;
    if (i >= NV) return;
    int rp = g_cursor[i] + g_boff[i >> 10];
    g_rowptr[i] = rp;
    g_cursor[i] = rp;
}

__global__ void z_scatter(const int* EI, const int* EA) {
    int e = blockIdx.x * blockDim.x + threadIdx.x;
    if (e >= NE) return;
    int d = EI[NE + e];
    if (d < 0) d = 0;
    if (d >= NV) d = NV - 1;
    int pos = atomicAdd(&g_cursor[d], 1);
    if (pos < 0) pos = 0;
    if (pos >= NE) pos = NE - 1;
    int s = EI[e];
    if (s < 0) s = 0;
    if (s >= NV) s = NV - 1;
    int b = EA[2 * e];
    if (b < 0) b = 0;
    if (b > 4) b = 4;
    int dr = EA[2 * e + 1];
    if (dr < 0) dr = 0;
    if (dr > 2) dr = 2;
    g_elist[pos] = s | ((b * 3 + dr) << 20);
}

// ================= aggregation with inline BN -> split bf16 output =================
__global__ void __launch_bounds__(256) k_agg(const float* __restrict__ EE1,
                                             const float* __restrict__ EE2,
                                             const float* __restrict__ EPS,
                                             int l, int dorelu) {
    __shared__ __align__(16) float etab[15 * F];
    int t = threadIdx.x;
    for (int j = t; j < 15 * F; j += 256) {
        int c = j >> 7, f = j & 127;
        etab[j] = EE1[(l * 5 + c / 3) * F + f] + EE2[(l * 3 + c % 3) * F + f];
    }
    __syncthreads();
    int gw = blockIdx.x * 8 + (t >> 5);
    int lane = t & 31;
    if (gw >= NV) return;
    float ep1 = 1.0f + EPS[l];
    const float4* Gv = (const float4*)Obuf;
    const float4* et = (const float4*)etab;
    float4 sc = ((const float4*)Scale_)[lane];
    float4 sh = ((const float4*)Shift_)[lane];

    float4 g = Gv[(size_t)gw * 32 + lane];
    float4 hn;
    hn.x = fmaf(g.x, sc.x, sh.x);
    hn.y = fmaf(g.y, sc.y, sh.y);
    hn.z = fmaf(g.z, sc.z, sh.z);
    hn.w = fmaf(g.w, sc.w, sh.w);
    if (dorelu) {
        hn.x = fmaxf(hn.x, 0.f); hn.y = fmaxf(hn.y, 0.f);
        hn.z = fmaxf(hn.z, 0.f); hn.w = fmaxf(hn.w, 0.f);
    }
    float4 e0 = et[lane];
    float4 acc;
    acc.x = ep1 * hn.x + fmaxf(hn.x + e0.x, 0.f);
    acc.y = ep1 * hn.y + fmaxf(hn.y + e0.y, 0.f);
    acc.z = ep1 * hn.z + fmaxf(hn.z + e0.z, 0.f);
    acc.w = ep1 * hn.w + fmaxf(hn.w + e0.w, 0.f);

    int beg = g_rowptr[gw];
    int end = g_rowptr[gw + 1];
    if (beg < 0) beg = 0;
    if (end > NE) end = NE;
    for (int base = beg; base < end; base += 32) {
        int n = end - base;
        if (n > 32) n = 32;
        int p = 0;
        if (lane < n) p = g_elist[base + lane];
        for (int j = 0; j < n; j++) {
            int pj = __shfl_sync(0xFFFFFFFF, p, j);
            int src = pj & 0xFFFFF;
            int code = (pj >> 20) & 15;
            if (src >= NV) src = NV - 1;
            if (code > 14) code = 14;
            float4 gs = __ldg(&Gv[(size_t)src * 32 + lane]);
            float4 hs;
            hs.x = fmaf(gs.x, sc.x, sh.x);
            hs.y = fmaf(gs.y, sc.y, sh.y);
            hs.z = fmaf(gs.z, sc.z, sh.z);
            hs.w = fmaf(gs.w, sc.w, sh.w);
            if (dorelu) {
                hs.x = fmaxf(hs.x, 0.f); hs.y = fmaxf(hs.y, 0.f);
                hs.z = fmaxf(hs.z, 0.f); hs.w = fmaxf(hs.w, 0.f);
            }
            float4 ev = et[code * 32 + lane];
            acc.x += fmaxf(hs.x + ev.x, 0.f);
            acc.y += fmaxf(hs.y + ev.y, 0.f);
            acc.z += fmaxf(hs.z + ev.z, 0.f);
            acc.w += fmaxf(hs.w + ev.w, 0.f);
        }
    }
    // split fp32 aggregate -> bf16 hi/lo, packed as 2x uint32 per lane
    uint32_t lo0, lo1;
    uint32_t hi0 = pack2(acc.x, acc.y, lo0);
    uint32_t hi1 = pack2(acc.z, acc.w, lo1);
    uint2* dh = (uint2*)((uint32_t*)AggHi + (size_t)gw * 64 + lane * 2);
    uint2* dl = (uint2*)((uint32_t*)AggLo + (size_t)gw * 64 + lane * 2);
    *dh = make_uint2(hi0, hi1);
    *dl = make_uint2(lo0, lo1);
}

// ================= BN finalize (also re-zeros accumulators) =================
__global__ void c_fin(const float* G, const float* B, int l) {
    int f = threadIdx.x;
    float mean = Sum_[f] / (float)NV;
    float var = Sq_[f] / (float)NV - mean * mean;
    if (var < 0.f) var = 0.f;
    float rstd = rsqrtf(var + 1e-5f);
    float sc = rstd * G[l * F + f];
    Scale_[f] = sc;
    Shift_[f] = B[l * F + f] - mean * sc;
    Sum_[f] = 0.f;
    Sq_[f] = 0.f;
}

__global__ void c_apply_last(float* dout) {
    long long idx = (long long)blockIdx.x * blockDim.x + threadIdx.x;
    if (idx >= (long long)NV * F) return;
    int f = (int)(idx % F);
    dout[idx] = Obuf[idx] * Scale_[f] + Shift_[f];
}

// ================= weight pre-split =================
__global__ void w_prep(const float* W1g, const float* W2g) {
    int idx = blockIdx.x * blockDim.x + threadIdx.x;
    if (idx < NL * F * F2) {
        int l = idx / (F * F2);
        int rem = idx % (F * F2);
        int k = rem / F2, n = rem % F2;
        __nv_bfloat16 h, lo;
        splitbf(W1g[idx], h, lo);
        W1Ht[((size_t)l * F2 + n) * F + k] = h;
        W1Lt[((size_t)l * F2 + n) * F + k] = lo;
        int k2 = rem / F, n2 = rem % F;
        splitbf(W2g[idx], h, lo);
        W2Ht[((size_t)l * F + n2) * F2 + k2] = h;
        W2Lt[((size_t)l * F + n2) * F2 + k2] = lo;
    }
}

// ================= mma.sync split-bf16 GEMM =================
__device__ __forceinline__ uint32_t s2u(const void* p) {
    return (uint32_t)__cvta_generic_to_shared(p);
}

__device__ __forceinline__ void ldsm4(uint32_t& r0, uint32_t& r1, uint32_t& r2,
                                      uint32_t& r3, uint32_t a) {
    asm volatile("ldmatrix.sync.aligned.m8n8.x4.shared.b16 {%0,%1,%2,%3}, [%4];"
                 : "=r"(r0), "=r"(r1), "=r"(r2), "=r"(r3) : "r"(a));
}

__device__ __forceinline__ void mmabf(float* c,
                                      uint32_t a0, uint32_t a1, uint32_t a2, uint32_t a3,
                                      uint32_t b0, uint32_t b1) {
    asm volatile(
        "mma.sync.aligned.m16n8k16.row.col.f32.bf16.bf16.f32 "
        "{%0,%1,%2,%3},{%4,%5,%6,%7},{%8,%9},{%0,%1,%2,%3};"
        : "+f"(c[0]), "+f"(c[1]), "+f"(c[2]), "+f"(c[3])
        : "r"(a0), "r"(a1), "r"(a2), "r"(a3), "r"(b0), "r"(b1));
}

extern __shared__ __align__(16) char dsm[];

// ---- GEMM1: Mid = split(relu(Agg @ W1 + b1)). CTA: M=64, N=128 (grid.y=2) ----
__global__ void __launch_bounds__(256) g1(const float* __restrict__ B1g, int l) {
    const int SA = 136;
    __nv_bfloat16* AH = (__nv_bfloat16*)dsm;      // 64*136
    __nv_bfloat16* AL = AH + 64 * SA;
    __nv_bfloat16* BH = AL + 64 * SA;             // 128*136
    __nv_bfloat16* BL = BH + 128 * SA;
    int tid = threadIdx.x;
    int row0 = blockIdx.x * 64;
    int ncol0 = blockIdx.y * 128;

    // stage A: pre-split Agg, pure uint32 copies
    {
        const uint32_t* GH = (const uint32_t*)AggHi;
        const uint32_t* GL = (const uint32_t*)AggLo;
        uint32_t* AH32 = (uint32_t*)AH;
        uint32_t* AL32 = (uint32_t*)AL;
        for (int idx = tid; idx < 64 * 64; idx += 256) {
            int m = idx >> 6, k2 = idx & 63;
            int row = row0 + m;
            uint32_t h = 0, lo = 0;
            if (row < NV) {
                h = GH[(size_t)row * 64 + k2];
                lo = GL[(size_t)row * 64 + k2];
            }
            AH32[m * 68 + k2] = h;
            AL32[m * 68 + k2] = lo;
        }
    }
    // stage B: pre-split W1
    {
        const uint32_t* WH = (const uint32_t*)W1Ht + ((size_t)l * F2 + ncol0) * 64;
        const uint32_t* WL = (const uint32_t*)W1Lt + ((size_t)l * F2 + ncol0) * 64;
        uint32_t* BH32 = (uint32_t*)BH;
        uint32_t* BL32 = (uint32_t*)BL;
        for (int idx = tid; idx < 128 * 64; idx += 256) {
            int n = idx >> 6, k2 = idx & 63;
            BH32[n * 68 + k2] = WH[n * 64 + k2];
            BL32[n * 68 + k2] = WL[n * 64 + k2];
        }
    }
    __syncthreads();

    int lane = tid & 31, wid = tid >> 5;
    int wm = wid & 1, wn = wid >> 1;   // rows wm*32..+31 (2 mt), cols wn*32..+31 (2 np)
    int lrow = lane & 15, lkof = (lane >> 4) * 8;

    float acc[2][4][4];
#pragma unroll
    for (int a = 0; a < 2; a++)
#pragma unroll
        for (int i = 0; i < 4; i++)
#pragma unroll
            for (int j = 0; j < 4; j++) acc[a][i][j] = 0.f;

#pragma unroll
    for (int ks = 0; ks < 8; ks++) {
        int kk = ks * 16 + lkof;
#pragma unroll
        for (int mt = 0; mt < 2; mt++) {
            uint32_t ah0, ah1, ah2, ah3, al0, al1, al2, al3;
            ldsm4(ah0, ah1, ah2, ah3,
                  s2u(AH + (wm * 32 + mt * 16 + lrow) * SA + kk));
            ldsm4(al0, al1, al2, al3,
                  s2u(AL + (wm * 32 + mt * 16 + lrow) * SA + kk));
#pragma unroll
            for (int np = 0; np < 2; np++) {
                int nrow = wn * 32 + np * 16 + lrow;
                uint32_t bh0, bh1, bh2, bh3, bl0, bl1, bl2, bl3;
                ldsm4(bh0, bh1, bh2, bh3, s2u(BH + nrow * SA + kk));
                ldsm4(bl0, bl1, bl2, bl3, s2u(BL + nrow * SA + kk));
                mmabf(acc[mt][2 * np], ah0, ah1, ah2, ah3, bh0, bh2);
                mmabf(acc[mt][2 * np], ah0, ah1, ah2, ah3, bl0, bl2);
                mmabf(acc[mt][2 * np], al0, al1, al2, al3, bh0, bh2);
                mmabf(acc[mt][2 * np + 1], ah0, ah1, ah2, ah3, bh1, bh3);
                mmabf(acc[mt][2 * np + 1], ah0, ah1, ah2, ah3, bl1, bl3);
                mmabf(acc[mt][2 * np + 1], al0, al1, al2, al3, bh1, bh3);
            }
        }
    }

    const float* bias = B1g + l * F2;
    int r = lane >> 2, cp = (lane & 3) * 2;
#pragma unroll
    for (int mt = 0; mt < 2; mt++) {
#pragma unroll
        for (int nt = 0; nt < 4; nt++) {
            int col = ncol0 + wn * 32 + nt * 8 + cp;
            float b0 = __ldg(bias + col), b1 = __ldg(bias + col + 1);
#pragma unroll
            for (int half = 0; half < 2; half++) {
                int row = row0 + wm * 32 + mt * 16 + r + half * 8;
                if (row < NV) {
                    float v0 = fmaxf(acc[mt][nt][2 * half + 0] + b0, 0.f);
                    float v1 = fmaxf(acc[mt][nt][2 * half + 1] + b1, 0.f);
                    uint32_t lw;
                    uint32_t hw = pack2(v0, v1, lw);
                    *(uint32_t*)(MidHi + (size_t)row * F2 + col) = hw;
                    *(uint32_t*)(MidLo + (size_t)row * F2 + col) = lw;
                }
            }
        }
    }
}

// ---- GEMM2: Obuf = Mid @ W2 + b2 (+ fused BN stats) ----
__global__ void __launch_bounds__(256) g2(const float* __restrict__ B2g, int l) {
    const int SA = 136;
    __nv_bfloat16* AH = (__nv_bfloat16*)dsm;
    __nv_bfloat16* AL = AH + 64 * SA;
    __nv_bfloat16* BH = AL + 64 * SA;
    __nv_bfloat16* BL = BH + 128 * SA;
    int tid = threadIdx.x;
    int row0 = blockIdx.x * 64;
    int lane = tid & 31, wid = tid >> 5;
    int wm = wid & 1, wn = wid >> 1;
    int lrow = lane & 15, lkof = (lane >> 4) * 8;

    float acc[2][4][4];
#pragma unroll
    for (int a = 0; a < 2; a++)
#pragma unroll
        for (int i = 0; i < 4; i++)
#pragma unroll
            for (int j = 0; j < 4; j++) acc[a][i][j] = 0.f;

    for (int pass = 0; pass < 2; pass++) {
        if (pass) __syncthreads();
        {
            const uint32_t* MH = (const uint32_t*)MidHi;
            const uint32_t* ML = (const uint32_t*)MidLo;
            uint32_t* AH32 = (uint32_t*)AH;
            uint32_t* AL32 = (uint32_t*)AL;
            for (int idx = tid; idx < 64 * 64; idx += 256) {
                int m = idx >> 6, k2 = idx & 63;
                int row = row0 + m;
                uint32_t h = 0, lo = 0;
                if (row < NV) {
                    h = MH[(size_t)row * 128 + pass * 64 + k2];
                    lo = ML[(size_t)row * 128 + pass * 64 + k2];
                }
                AH32[m * 68 + k2] = h;
                AL32[m * 68 + k2] = lo;
            }
        }
        {
            const uint32_t* WH = (const uint32_t*)W2Ht + (size_t)l * F * 128;
            const uint32_t* WL = (const uint32_t*)W2Lt + (size_t)l * F * 128;
            uint32_t* BH32 = (uint32_t*)BH;
            uint32_t* BL32 = (uint32_t*)BL;
            for (int idx = tid; idx < 128 * 64; idx += 256) {
                int n = idx >> 6, k2 = idx & 63;
                BH32[n * 68 + k2] = WH[n * 128 + pass * 64 + k2];
                BL32[n * 68 + k2] = WL[n * 128 + pass * 64 + k2];
            }
        }
        __syncthreads();

#pragma unroll
        for (int ks = 0; ks < 8; ks++) {
            int kk = ks * 16 + lkof;
#pragma unroll
            for (int mt = 0; mt < 2; mt++) {
                uint32_t ah0, ah1, ah2, ah3, al0, al1, al2, al3;
                ldsm4(ah0, ah1, ah2, ah3,
                      s2u(AH + (wm * 32 + mt * 16 + lrow) * SA + kk));
                ldsm4(al0, al1, al2, al3,
                      s2u(AL + (wm * 32 + mt * 16 + lrow) * SA + kk));
#pragma unroll
                for (int np = 0; np < 2; np++) {
                    int nrow = wn * 32 + np * 16 + lrow;
                    uint32_t bh0, bh1, bh2, bh3, bl0, bl1, bl2, bl3;
                    ldsm4(bh0, bh1, bh2, bh3, s2u(BH + nrow * SA + kk));
                    ldsm4(bl0, bl1, bl2, bl3, s2u(BL + nrow * SA + kk));
                    mmabf(acc[mt][2 * np], ah0, ah1, ah2, ah3, bh0, bh2);
                    mmabf(acc[mt][2 * np], ah0, ah1, ah2, ah3, bl0, bl2);
                    mmabf(acc[mt][2 * np], al0, al1, al2, al3, bh0, bh2);
                    mmabf(acc[mt][2 * np + 1], ah0, ah1, ah2, ah3, bh1, bh3);
                    mmabf(acc[mt][2 * np + 1], ah0, ah1, ah2, ah3, bl1, bl3);
                    mmabf(acc[mt][2 * np + 1], al0, al1, al2, al3, bh1, bh3);
                }
            }
        }
    }

    const float* bias = B2g + l * F;
    int r = lane >> 2, cp = (lane & 3) * 2;
    float lsum[4][2], lsq[4][2];
#pragma unroll
    for (int nt = 0; nt < 4; nt++) {
        lsum[nt][0] = 0.f; lsum[nt][1] = 0.f;
        lsq[nt][0] = 0.f; lsq[nt][1] = 0.f;
    }
#pragma unroll
    for (int mt = 0; mt < 2; mt++) {
#pragma unroll
        for (int nt = 0; nt < 4; nt++) {
            int col = wn * 32 + nt * 8 + cp;
            float b0 = __ldg(bias + col), b1 = __ldg(bias + col + 1);
#pragma unroll
            for (int half = 0; half < 2; half++) {
                int row = row0 + wm * 32 + mt * 16 + r + half * 8;
                if (row < NV) {
                    float2 o;
                    o.x = acc[mt][nt][2 * half + 0] + b0;
                    o.y = acc[mt][nt][2 * half + 1] + b1;
                    *(float2*)(Obuf + (size_t)row * F + col) = o;
                    lsum[nt][0] += o.x; lsum[nt][1] += o.y;
                    lsq[nt][0] += o.x * o.x; lsq[nt][1] += o.y * o.y;
                }
            }
        }
    }
#pragma unroll
    for (int nt = 0; nt < 4; nt++) {
#pragma unroll
        for (int c = 0; c < 2; c++) {
#pragma unroll
            for (int off = 4; off < 32; off <<= 1) {
                lsum[nt][c] += __shfl_xor_sync(0xFFFFFFFF, lsum[nt][c], off);
                lsq[nt][c] += __shfl_xor_sync(0xFFFFFFFF, lsq[nt][c], off);
            }
        }
    }
    if (lane < 4) {
#pragma unroll
        for (int nt = 0; nt < 4; nt++) {
            int col = wn * 32 + nt * 8 + lane * 2;
            atomicAdd(&Sum_[col], lsum[nt][0]);
            atomicAdd(&Sum_[col + 1], lsum[nt][1]);
            atomicAdd(&Sq_[col], lsq[nt][0]);
            atomicAdd(&Sq_[col + 1], lsq[nt][1]);
        }
    }
}

// ================= launch =================
extern "C" void kernel_launch(void* const* d_in, const int* in_sizes, int n_in,
                              void* d_out, int out_size) {
    const int*   X   = (const int*)d_in[0];
    const int*   EI  = (const int*)d_in[1];
    const int*   EA  = (const int*)d_in[2];
    const float* XE1 = (const float*)d_in[3];
    const float* XE2 = (const float*)d_in[4];
    const float* EE1 = (const float*)d_in[5];
    const float* EE2 = (const float*)d_in[6];
    const float* W1g = (const float*)d_in[7];
    const float* B1g = (const float*)d_in[8];
    const float* W2g = (const float*)d_in[9];
    const float* B2g = (const float*)d_in[10];
    const float* EPS = (const float*)d_in[11];
    const float* G   = (const float*)d_in[12];
    const float* B   = (const float*)d_in[13];
    float* dout = (float*)d_out;

    const int SMG = (64 * 136 * 2 + 128 * 136 * 2) * 2;  // 104448 B
    cudaFuncSetAttribute(g1, cudaFuncAttributeMaxDynamicSharedMemorySize, SMG);
    cudaFuncSetAttribute(g2, cudaFuncAttributeMaxDynamicSharedMemorySize, SMG);

    long long nvf = (long long)NV * F;
    int gb_n = (int)((nvf + 255) / 256);

    w_prep<<<(NL * F * F2 + 255) / 256, 256>>>(W1g, W2g);
    c_init<<<gb_n, 256>>>(X, XE1, XE2);
    z_init_bn<<<1, 128>>>();
    z_zero<<<(NV + 255) / 256, 256>>>();
    z_count<<<(NE + 255) / 256, 256>>>(EI);
    int nb = (NV + 1023) / 1024;  // 98
    z_scan1<<<nb, 1024>>>();
    z_scan2<<<1, 128>>>(nb);
    z_scan3<<<(NV + 255) / 256, 256>>>();
    z_scatter<<<(NE + 255) / 256, 256>>>(EI, EA);

    dim3 grid1((NV + 63) / 64, 2);
    int grid2 = (NV + 63) / 64;
    int gagg = (NV + 7) / 8;  // 12500
    for (int l = 0; l < NL; l++) {
        k_agg<<<gagg, 256>>>(EE1, EE2, EPS, l, l > 0 ? 1 : 0);
        g1<<<grid1, 256, SMG>>>(B1g, l);
        g2<<<grid2, 256, SMG>>>(B2g, l);
        c_fin<<<1, 128>>>(G, B, l);
    }
    c_apply_last<<<gb_n, 256>>>(dout);
}

// round 16
// speedup vs baseline: 3.9486x; 1.4034x over previous
#include <cuda_runtime.h>
#include <cuda_bf16.h>
#include <stdint.h>

#define NV 100000
#define NE 600000
#define F 128
#define F2 256
#define NL 5

// ---------------- scratch ----------------
__device__ float Obuf[NV * F];                    // GEMM2 output (pre-BN h)
__device__ __nv_bfloat16 AggHi[(size_t)NV * F];   // aggregate, split bf16
__device__ __nv_bfloat16 AggLo[(size_t)NV * F];
__device__ __nv_bfloat16 MidHi[(size_t)NV * F2];
__device__ __nv_bfloat16 MidLo[(size_t)NV * F2];
__device__ float Sum_[F];
__device__ float Sq_[F];
__device__ float Scale_[F];
__device__ float Shift_[F];
__device__ __nv_bfloat16 W1Ht[NL * F2 * F];
__device__ __nv_bfloat16 W1Lt[NL * F2 * F];
__device__ __nv_bfloat16 W2Ht[NL * F * F2];
__device__ __nv_bfloat16 W2Lt[NL * F * F2];
// CSR by destination
__device__ int g_cnt[NV];
__device__ int g_cursor[NV];
__device__ int g_rowptr[NV + 1];
__device__ int g_bsum[128];
__device__ int g_boff[128];
__device__ int g_elist[NE];   // src | code<<20

__device__ __forceinline__ void splitbf(float v, __nv_bfloat16& h, __nv_bfloat16& lo) {
    h = __float2bfloat16(v);
    lo = __float2bfloat16(v - __bfloat162float(h));
}

__device__ __forceinline__ uint32_t pack2(float v0, float v1, uint32_t& lo_out) {
    __nv_bfloat16 h0, l0, h1, l1;
    splitbf(v0, h0, l0);
    splitbf(v1, h1, l1);
    lo_out = (uint32_t)__bfloat16_as_ushort(l0) |
             ((uint32_t)__bfloat16_as_ushort(l1) << 16);
    return (uint32_t)__bfloat16_as_ushort(h0) |
           ((uint32_t)__bfloat16_as_ushort(h1) << 16);
}

// ---------------- cp.async helpers ----------------
__device__ __forceinline__ uint32_t s2u(const void* p) {
    return (uint32_t)__cvta_generic_to_shared(p);
}

__device__ __forceinline__ void cpa16(uint32_t dst, const void* src) {
    asm volatile("cp.async.ca.shared.global [%0], [%1], 16;"
                 :: "r"(dst), "l"(src));
}

__device__ __forceinline__ void cpa16p(uint32_t dst, const void* src, int srcbytes) {
    asm volatile("cp.async.ca.shared.global [%0], [%1], 16, %2;"
                 :: "r"(dst), "l"(src), "r"(srcbytes));
}

#define CP_COMMIT() asm volatile("cp.async.commit_group;" ::: "memory")
#define CP_WAIT0()  asm volatile("cp.async.wait_group 0;" ::: "memory")

// ================= merged prep: weights + h0 + BN identity + cnt zero =================
__global__ void prep_all(const int* X, const float* XE1, const float* XE2,
                         const float* W1g, const float* W2g) {
    long long idx = (long long)blockIdx.x * blockDim.x + threadIdx.x;
    // h0
    if (idx < (long long)NV * F) {
        int v = (int)(idx / F);
        int f = (int)(idx % F);
        int atom = X[2 * v];
        if (atom < 0) atom = 0;
        if (atom > 118) atom = 118;
        int chir = X[2 * v + 1];
        if (chir < 0) chir = 0;
        if (chir > 2) chir = 2;
        Obuf[idx] = XE1[atom * F + f] + XE2[chir * F + f];
    }
    // weight pre-split
    if (idx < NL * F * F2) {
        int l = (int)(idx / (F * F2));
        int rem = (int)(idx % (F * F2));
        int k = rem / F2, n = rem % F2;
        __nv_bfloat16 h, lo;
        splitbf(W1g[idx], h, lo);
        W1Ht[((size_t)l * F2 + n) * F + k] = h;
        W1Lt[((size_t)l * F2 + n) * F + k] = lo;
        int k2 = rem / F, n2 = rem % F;
        splitbf(W2g[idx], h, lo);
        W2Ht[((size_t)l * F + n2) * F2 + k2] = h;
        W2Lt[((size_t)l * F + n2) * F2 + k2] = lo;
    }
    // cnt zero + BN identity
    if (idx < NV) g_cnt[idx] = 0;
    if (idx < F) {
        Sum_[idx] = 0.f;
        Sq_[idx] = 0.f;
        Scale_[idx] = 1.f;
        Shift_[idx] = 0.f;
    }
}

// ================= CSR build =================
__global__ void z_count(const int* EI) {
    int e = blockIdx.x * blockDim.x + threadIdx.x;
    if (e >= NE) return;
    int d = EI[NE + e];
    if (d < 0) d = 0;
    if (d >= NV) d = NV - 1;
    atomicAdd(&g_cnt[d], 1);
}

__global__ void z_scan1() {
    __shared__ int s[1024];
    int t = threadIdx.x;
    int gi = blockIdx.x * 1024 + t;
    int v = (gi < NV) ? g_cnt[gi] : 0;
    s[t] = v;
    __syncthreads();
    for (int off = 1; off < 1024; off <<= 1) {
        int xv = 0;
        if (t >= off) xv = s[t - off];
        __syncthreads();
        s[t] += xv;
        __syncthreads();
    }
    if (gi < NV) g_cursor[gi] = s[t] - v;
    if (t == 1023) g_bsum[blockIdx.x] = s[t];
}

__global__ void z_scan2(int nb) {
    __shared__ int s[128];
    int t = threadIdx.x;
    int v = (t < nb) ? g_bsum[t] : 0;
    s[t] = v;
    __syncthreads();
    for (int off = 1; off < 128; off <<= 1) {
        int xv = 0;
        if (t >= off) xv = s[t - off];
        __syncthreads();
        s[t] += xv;
        __syncthreads();
    }
    g_boff[t] = s[t] - v;
    if (t == 0) g_rowptr[NV] = NE;
}

__global__ void z_scan3() {
    int i = blockIdx.x * blockDim.x + threadIdx.x;
    if (i >= NV) return;
    int rp = g_cursor[i] + g_boff[i >> 10];
    g_rowptr[i] = rp;
    g_cursor[i] = rp;
}

__global__ void z_scatter(const int* EI, const int* EA) {
    int e = blockIdx.x * blockDim.x + threadIdx.x;
    if (e >= NE) return;
    int d = EI[NE + e];
    if (d < 0) d = 0;
    if (d >= NV) d = NV - 1;
    int pos = atomicAdd(&g_cursor[d], 1);
    if (pos < 0) pos = 0;
    if (pos >= NE) pos = NE - 1;
    int s = EI[e];
    if (s < 0) s = 0;
    if (s >= NV) s = NV - 1;
    int b = EA[2 * e];
    if (b < 0) b = 0;
    if (b > 4) b = 4;
    int dr = EA[2 * e + 1];
    if (dr < 0) dr = 0;
    if (dr > 2) dr = 2;
    g_elist[pos] = s | ((b * 3 + dr) << 20);
}

// ================= aggregation with inline BN -> split bf16 output =================
__device__ __forceinline__ float4 bn4(float4 g, float4 sc, float4 sh, int dorelu) {
    float4 h;
    h.x = fmaf(g.x, sc.x, sh.x);
    h.y = fmaf(g.y, sc.y, sh.y);
    h.z = fmaf(g.z, sc.z, sh.z);
    h.w = fmaf(g.w, sc.w, sh.w);
    if (dorelu) {
        h.x = fmaxf(h.x, 0.f); h.y = fmaxf(h.y, 0.f);
        h.z = fmaxf(h.z, 0.f); h.w = fmaxf(h.w, 0.f);
    }
    return h;
}

__global__ void __launch_bounds__(256) k_agg(const float* __restrict__ EE1,
                                             const float* __restrict__ EE2,
                                             const float* __restrict__ EPS,
                                             int l, int dorelu) {
    __shared__ __align__(16) float etab[15 * F];
    int t = threadIdx.x;
    for (int j = t; j < 15 * F; j += 256) {
        int c = j >> 7, f = j & 127;
        etab[j] = EE1[(l * 5 + c / 3) * F + f] + EE2[(l * 3 + c % 3) * F + f];
    }
    __syncthreads();
    int gw = blockIdx.x * 8 + (t >> 5);
    int lane = t & 31;
    if (gw >= NV) return;
    float ep1 = 1.0f + EPS[l];
    const float4* Gv = (const float4*)Obuf;
    const float4* et = (const float4*)etab;
    float4 sc = ((const float4*)Scale_)[lane];
    float4 sh = ((const float4*)Shift_)[lane];

    float4 hn = bn4(Gv[(size_t)gw * 32 + lane], sc, sh, dorelu);
    float4 e0 = et[lane];
    float4 acc;
    acc.x = ep1 * hn.x + fmaxf(hn.x + e0.x, 0.f);
    acc.y = ep1 * hn.y + fmaxf(hn.y + e0.y, 0.f);
    acc.z = ep1 * hn.z + fmaxf(hn.z + e0.z, 0.f);
    acc.w = ep1 * hn.w + fmaxf(hn.w + e0.w, 0.f);

    int beg = g_rowptr[gw];
    int end = g_rowptr[gw + 1];
    if (beg < 0) beg = 0;
    if (end > NE) end = NE;
    for (int base = beg; base < end; base += 32) {
        int n = end - base;
        if (n > 32) n = 32;
        int p = 0;
        if (lane < n) p = g_elist[base + lane];
        int j = 0;
        // 4-wide: issue 4 independent loads before consuming
        for (; j + 4 <= n; j += 4) {
            int p0 = __shfl_sync(0xFFFFFFFF, p, j);
            int p1 = __shfl_sync(0xFFFFFFFF, p, j + 1);
            int p2 = __shfl_sync(0xFFFFFFFF, p, j + 2);
            int p3 = __shfl_sync(0xFFFFFFFF, p, j + 3);
            int s0 = p0 & 0xFFFFF, s1 = p1 & 0xFFFFF;
            int s2 = p2 & 0xFFFFF, s3 = p3 & 0xFFFFF;
            float4 g0 = __ldg(&Gv[(size_t)s0 * 32 + lane]);
            float4 g1v = __ldg(&Gv[(size_t)s1 * 32 + lane]);
            float4 g2v = __ldg(&Gv[(size_t)s2 * 32 + lane]);
            float4 g3 = __ldg(&Gv[(size_t)s3 * 32 + lane]);
            float4 h0 = bn4(g0, sc, sh, dorelu);
            float4 h1 = bn4(g1v, sc, sh, dorelu);
            float4 h2 = bn4(g2v, sc, sh, dorelu);
            float4 h3 = bn4(g3, sc, sh, dorelu);
            float4 e0v = et[((p0 >> 20) & 15) * 32 + lane];
            float4 e1v = et[((p1 >> 20) & 15) * 32 + lane];
            float4 e2v = et[((p2 >> 20) & 15) * 32 + lane];
            float4 e3v = et[((p3 >> 20) & 15) * 32 + lane];
            acc.x += fmaxf(h0.x + e0v.x, 0.f) + fmaxf(h1.x + e1v.x, 0.f) +
                     fmaxf(h2.x + e2v.x, 0.f) + fmaxf(h3.x + e3v.x, 0.f);
            acc.y += fmaxf(h0.y + e0v.y, 0.f) + fmaxf(h1.y + e1v.y, 0.f) +
                     fmaxf(h2.y + e2v.y, 0.f) + fmaxf(h3.y + e3v.y, 0.f);
            acc.z += fmaxf(h0.z + e0v.z, 0.f) + fmaxf(h1.z + e1v.z, 0.f) +
                     fmaxf(h2.z + e2v.z, 0.f) + fmaxf(h3.z + e3v.z, 0.f);
            acc.w += fmaxf(h0.w + e0v.w, 0.f) + fmaxf(h1.w + e1v.w, 0.f) +
                     fmaxf(h2.w + e2v.w, 0.f) + fmaxf(h3.w + e3v.w, 0.f);
        }
        for (; j < n; j++) {
            int pj = __shfl_sync(0xFFFFFFFF, p, j);
            int src = pj & 0xFFFFF;
            int code = (pj >> 20) & 15;
            float4 gs = __ldg(&Gv[(size_t)src * 32 + lane]);
            float4 hs = bn4(gs, sc, sh, dorelu);
            float4 ev = et[code * 32 + lane];
            acc.x += fmaxf(hs.x + ev.x, 0.f);
            acc.y += fmaxf(hs.y + ev.y, 0.f);
            acc.z += fmaxf(hs.z + ev.z, 0.f);
            acc.w += fmaxf(hs.w + ev.w, 0.f);
        }
    }
    uint32_t lo0, lo1;
    uint32_t hi0 = pack2(acc.x, acc.y, lo0);
    uint32_t hi1 = pack2(acc.z, acc.w, lo1);
    *(uint2*)((uint32_t*)AggHi + (size_t)gw * 64 + lane * 2) = make_uint2(hi0, hi1);
    *(uint2*)((uint32_t*)AggLo + (size_t)gw * 64 + lane * 2) = make_uint2(lo0, lo1);
}

// ================= BN finalize =================
__global__ void c_fin(const float* G, const float* B, int l) {
    int f = threadIdx.x;
    float mean = Sum_[f] / (float)NV;
    float var = Sq_[f] / (float)NV - mean * mean;
    if (var < 0.f) var = 0.f;
    float rstd = rsqrtf(var + 1e-5f);
    float sc = rstd * G[l * F + f];
    Scale_[f] = sc;
    Shift_[f] = B[l * F + f] - mean * sc;
    Sum_[f] = 0.f;
    Sq_[f] = 0.f;
}

__global__ void c_apply_last(float* dout) {
    long long idx = (long long)blockIdx.x * blockDim.x + threadIdx.x;
    if (idx >= (long long)NV * F) return;
    int f = (int)(idx % F);
    dout[idx] = Obuf[idx] * Scale_[f] + Shift_[f];
}

// ================= mma.sync split-bf16 GEMM =================
__device__ __forceinline__ void ldsm4(uint32_t& r0, uint32_t& r1, uint32_t& r2,
                                      uint32_t& r3, uint32_t a) {
    asm volatile("ldmatrix.sync.aligned.m8n8.x4.shared.b16 {%0,%1,%2,%3}, [%4];"
                 : "=r"(r0), "=r"(r1), "=r"(r2), "=r"(r3) : "r"(a));
}

__device__ __forceinline__ void mmabf(float* c,
                                      uint32_t a0, uint32_t a1, uint32_t a2, uint32_t a3,
                                      uint32_t b0, uint32_t b1) {
    asm volatile(
        "mma.sync.aligned.m16n8k16.row.col.f32.bf16.bf16.f32 "
        "{%0,%1,%2,%3},{%4,%5,%6,%7},{%8,%9},{%0,%1,%2,%3};"
        : "+f"(c[0]), "+f"(c[1]), "+f"(c[2]), "+f"(c[3])
        : "r"(a0), "r"(a1), "r"(a2), "r"(a3), "r"(b0), "r"(b1));
}

extern __shared__ __align__(16) char dsm[];

// ---- GEMM1: Mid = split(relu(Agg @ W1 + b1)). CTA: M=64, N=128 (grid.y=2) ----
__global__ void __launch_bounds__(256) g1(const float* __restrict__ B1g, int l) {
    const int SA = 136;
    __nv_bfloat16* AH = (__nv_bfloat16*)dsm;
    __nv_bfloat16* AL = AH + 64 * SA;
    __nv_bfloat16* BH = AL + 64 * SA;
    __nv_bfloat16* BL = BH + 128 * SA;
    int tid = threadIdx.x;
    int row0 = blockIdx.x * 64;
    int ncol0 = blockIdx.y * 128;

    // stage A via cp.async (16B chunks); OOB rows zero-filled via src-size=0
    {
        const uint32_t* GH = (const uint32_t*)AggHi;
        const uint32_t* GL = (const uint32_t*)AggLo;
        uint32_t ah = s2u(AH), al = s2u(AL);
        for (int idx = tid; idx < 64 * 16; idx += 256) {
            int m = idx >> 4, c4 = (idx & 15) * 4;
            int row = row0 + m;
            int sb = (row < NV) ? 16 : 0;
            const uint32_t* srch = GH + (size_t)row * 64 + c4;
            const uint32_t* srcl = GL + (size_t)row * 64 + c4;
            cpa16p(ah + (m * 68 + c4) * 4, srch, sb);
            cpa16p(al + (m * 68 + c4) * 4, srcl, sb);
        }
    }
    // stage B via cp.async
    {
        const uint32_t* WH = (const uint32_t*)W1Ht + ((size_t)l * F2 + ncol0) * 64;
        const uint32_t* WL = (const uint32_t*)W1Lt + ((size_t)l * F2 + ncol0) * 64;
        uint32_t bh = s2u(BH), bl = s2u(BL);
        for (int idx = tid; idx < 128 * 16; idx += 256) {
            int n = idx >> 4, c4 = (idx & 15) * 4;
            cpa16(bh + (n * 68 + c4) * 4, WH + n * 64 + c4);
            cpa16(bl + (n * 68 + c4) * 4, WL + n * 64 + c4);
        }
    }
    CP_COMMIT();
    CP_WAIT0();
    __syncthreads();

    int lane = tid & 31, wid = tid >> 5;
    int wm = wid & 1, wn = wid >> 1;
    int lrow = lane & 15, lkof = (lane >> 4) * 8;

    float acc[2][4][4];
#pragma unroll
    for (int a = 0; a < 2; a++)
#pragma unroll
        for (int i = 0; i < 4; i++)
#pragma unroll
            for (int j = 0; j < 4; j++) acc[a][i][j] = 0.f;

#pragma unroll
    for (int ks = 0; ks < 8; ks++) {
        int kk = ks * 16 + lkof;
#pragma unroll
        for (int mt = 0; mt < 2; mt++) {
            uint32_t ah0, ah1, ah2, ah3, al0, al1, al2, al3;
            ldsm4(ah0, ah1, ah2, ah3,
                  s2u(AH + (wm * 32 + mt * 16 + lrow) * SA + kk));
            ldsm4(al0, al1, al2, al3,
                  s2u(AL + (wm * 32 + mt * 16 + lrow) * SA + kk));
#pragma unroll
            for (int np = 0; np < 2; np++) {
                int nrow = wn * 32 + np * 16 + lrow;
                uint32_t bh0, bh1, bh2, bh3, bl0, bl1, bl2, bl3;
                ldsm4(bh0, bh1, bh2, bh3, s2u(BH + nrow * SA + kk));
                ldsm4(bl0, bl1, bl2, bl3, s2u(BL + nrow * SA + kk));
                mmabf(acc[mt][2 * np], ah0, ah1, ah2, ah3, bh0, bh2);
                mmabf(acc[mt][2 * np], ah0, ah1, ah2, ah3, bl0, bl2);
                mmabf(acc[mt][2 * np], al0, al1, al2, al3, bh0, bh2);
                mmabf(acc[mt][2 * np + 1], ah0, ah1, ah2, ah3, bh1, bh3);
                mmabf(acc[mt][2 * np + 1], ah0, ah1, ah2, ah3, bl1, bl3);
                mmabf(acc[mt][2 * np + 1], al0, al1, al2, al3, bh1, bh3);
            }
        }
    }

    const float* bias = B1g + l * F2;
    int r = lane >> 2, cp = (lane & 3) * 2;
#pragma unroll
    for (int mt = 0; mt < 2; mt++) {
#pragma unroll
        for (int nt = 0; nt < 4; nt++) {
            int col = ncol0 + wn * 32 + nt * 8 + cp;
            float b0 = __ldg(bias + col), b1 = __ldg(bias + col + 1);
#pragma unroll
            for (int half = 0; half < 2; half++) {
                int row = row0 + wm * 32 + mt * 16 + r + half * 8;
                if (row < NV) {
                    float v0 = fmaxf(acc[mt][nt][2 * half + 0] + b0, 0.f);
                    float v1 = fmaxf(acc[mt][nt][2 * half + 1] + b1, 0.f);
                    uint32_t lw;
                    uint32_t hw = pack2(v0, v1, lw);
                    *(uint32_t*)(MidHi + (size_t)row * F2 + col) = hw;
                    *(uint32_t*)(MidLo + (size_t)row * F2 + col) = lw;
                }
            }
        }
    }
}

// ---- GEMM2: Obuf = Mid @ W2 + b2 (+ fused BN stats) ----
__global__ void __launch_bounds__(256) g2(const float* __restrict__ B2g, int l) {
    const int SA = 136;
    __nv_bfloat16* AH = (__nv_bfloat16*)dsm;
    __nv_bfloat16* AL = AH + 64 * SA;
    __nv_bfloat16* BH = AL + 64 * SA;
    __nv_bfloat16* BL = BH + 128 * SA;
    int tid = threadIdx.x;
    int row0 = blockIdx.x * 64;
    int lane = tid & 31, wid = tid >> 5;
    int wm = wid & 1, wn = wid >> 1;
    int lrow = lane & 15, lkof = (lane >> 4) * 8;

    float acc[2][4][4];
#pragma unroll
    for (int a = 0; a < 2; a++)
#pragma unroll
        for (int i = 0; i < 4; i++)
#pragma unroll
            for (int j = 0; j < 4; j++) acc[a][i][j] = 0.f;

    for (int pass = 0; pass < 2; pass++) {
        if (pass) __syncthreads();
        {
            const uint32_t* MH = (const uint32_t*)MidHi;
            const uint32_t* ML = (const uint32_t*)MidLo;
            uint32_t ah = s2u(AH), al = s2u(AL);
            for (int idx = tid; idx < 64 * 16; idx += 256) {
                int m = idx >> 4, c4 = (idx & 15) * 4;
                int row = row0 + m;
                int sb = (row < NV) ? 16 : 0;
                cpa16p(ah + (m * 68 + c4) * 4,
                       MH + (size_t)row * 128 + pass * 64 + c4, sb);
                cpa16p(al + (m * 68 + c4) * 4,
                       ML + (size_t)row * 128 + pass * 64 + c4, sb);
            }
        }
        {
            const uint32_t* WH = (const uint32_t*)W2Ht + (size_t)l * F * 128;
            const uint32_t* WL = (const uint32_t*)W2Lt + (size_t)l * F * 128;
            uint32_t bh = s2u(BH), bl = s2u(BL);
            for (int idx = tid; idx < 128 * 16; idx += 256) {
                int n = idx >> 4, c4 = (idx & 15) * 4;
                cpa16(bh + (n * 68 + c4) * 4, WH + n * 128 + pass * 64 + c4);
                cpa16(bl + (n * 68 + c4) * 4, WL + n * 128 + pass * 64 + c4);
            }
        }
        CP_COMMIT();
        CP_WAIT0();
        __syncthreads();

#pragma unroll
        for (int ks = 0; ks < 8; ks++) {
            int kk = ks * 16 + lkof;
#pragma unroll
            for (int mt = 0; mt < 2; mt++) {
                uint32_t ah0, ah1, ah2, ah3, al0, al1, al2, al3;
                ldsm4(ah0, ah1, ah2, ah3,
                      s2u(AH + (wm * 32 + mt * 16 + lrow) * SA + kk));
                ldsm4(al0, al1, al2, al3,
                      s2u(AL + (wm * 32 + mt * 16 + lrow) * SA + kk));
#pragma unroll
                for (int np = 0; np < 2; np++) {
                    int nrow = wn * 32 + np * 16 + lrow;
                    uint32_t bh0, bh1, bh2, bh3, bl0, bl1, bl2, bl3;
                    ldsm4(bh0, bh1, bh2, bh3, s2u(BH + nrow * SA + kk));
                    ldsm4(bl0, bl1, bl2, bl3, s2u(BL + nrow * SA + kk));
                    mmabf(acc[mt][2 * np], ah0, ah1, ah2, ah3, bh0, bh2);
                    mmabf(acc[mt][2 * np], ah0, ah1, ah2, ah3, bl0, bl2);
                    mmabf(acc[mt][2 * np], al0, al1, al2, al3, bh0, bh2);
                    mmabf(acc[mt][2 * np + 1], ah0, ah1, ah2, ah3, bh1, bh3);
                    mmabf(acc[mt][2 * np + 1], ah0, ah1, ah2, ah3, bl1, bl3);
                    mmabf(acc[mt][2 * np + 1], al0, al1, al2, al3, bh1, bh3);
                }
            }
        }
    }

    const float* bias = B2g + l * F;
    int r = lane >> 2, cp = (lane & 3) * 2;
    float lsum[4][2], lsq[4][2];
#pragma unroll
    for (int nt = 0; nt < 4; nt++) {
        lsum[nt][0] = 0.f; lsum[nt][1] = 0.f;
        lsq[nt][0] = 0.f; lsq[nt][1] = 0.f;
    }
#pragma unroll
    for (int mt = 0; mt < 2; mt++) {
#pragma unroll
        for (int nt = 0; nt < 4; nt++) {
            int col = wn * 32 + nt * 8 + cp;
            float b0 = __ldg(bias + col), b1 = __ldg(bias + col + 1);
#pragma unroll
            for (int half = 0; half < 2; half++) {
                int row = row0 + wm * 32 + mt * 16 + r + half * 8;
                if (row < NV) {
                    float2 o;
                    o.x = acc[mt][nt][2 * half + 0] + b0;
                    o.y = acc[mt][nt][2 * half + 1] + b1;
                    *(float2*)(Obuf + (size_t)row * F + col) = o;
                    lsum[nt][0] += o.x; lsum[nt][1] += o.y;
                    lsq[nt][0] += o.x * o.x; lsq[nt][1] += o.y * o.y;
                }
            }
        }
    }
#pragma unroll
    for (int nt = 0; nt < 4; nt++) {
#pragma unroll
        for (int c = 0; c < 2; c++) {
#pragma unroll
            for (int off = 4; off < 32; off <<= 1) {
                lsum[nt][c] += __shfl_xor_sync(0xFFFFFFFF, lsum[nt][c], off);
                lsq[nt][c] += __shfl_xor_sync(0xFFFFFFFF, lsq[nt][c], off);
            }
        }
    }
    if (lane < 4) {
#pragma unroll
        for (int nt = 0; nt < 4; nt++) {
            int col = wn * 32 + nt * 8 + lane * 2;
            atomicAdd(&Sum_[col], lsum[nt][0]);
            atomicAdd(&Sum_[col + 1], lsum[nt][1]);
            atomicAdd(&Sq_[col], lsq[nt][0]);
            atomicAdd(&Sq_[col + 1], lsq[nt][1]);
        }
    }
}

// ================= launch =================
extern "C" void kernel_launch(void* const* d_in, const int* in_sizes, int n_in,
                              void* d_out, int out_size) {
    const int*   X   = (const int*)d_in[0];
    const int*   EI  = (const int*)d_in[1];
    const int*   EA  = (const int*)d_in[2];
    const float* XE1 = (const float*)d_in[3];
    const float* XE2 = (const float*)d_in[4];
    const float* EE1 = (const float*)d_in[5];
    const float* EE2 = (const float*)d_in[6];
    const float* W1g = (const float*)d_in[7];
    const float* B1g = (const float*)d_in[8];
    const float* W2g = (const float*)d_in[9];
    const float* B2g = (const float*)d_in[10];
    const float* EPS = (const float*)d_in[11];
    const float* G   = (const float*)d_in[12];
    const float* B   = (const float*)d_in[13];
    float* dout = (float*)d_out;

    const int SMG = (64 * 136 * 2 + 128 * 136 * 2) * 2;  // 104448 B
    cudaFuncSetAttribute(g1, cudaFuncAttributeMaxDynamicSharedMemorySize, SMG);
    cudaFuncSetAttribute(g2, cudaFuncAttributeMaxDynamicSharedMemorySize, SMG);

    long long nvf = (long long)NV * F;
    int gb_n = (int)((nvf + 255) / 256);

    prep_all<<<gb_n, 256>>>(X, XE1, XE2, W1g, W2g);
    z_count<<<(NE + 255) / 256, 256>>>(EI);
    int nb = (NV + 1023) / 1024;  // 98
    z_scan1<<<nb, 1024>>>();
    z_scan2<<<1, 128>>>(nb);
    z_scan3<<<(NV + 255) / 256, 256>>>();
    z_scatter<<<(NE + 255) / 256, 256>>>(EI, EA);

    dim3 grid1((NV + 63) / 64, 2);
    int grid2 = (NV + 63) / 64;
    int gagg = (NV + 7) / 8;  // 12500
    for (int l = 0; l < NL; l++) {
        k_agg<<<gagg, 256>>>(EE1, EE2, EPS, l, l > 0 ? 1 : 0);
        g1<<<grid1, 256, SMG>>>(B1g, l);
        g2<<<grid2, 256, SMG>>>(B2g, l);
        c_fin<<<1, 128>>>(G, B, l);
    }
    c_apply_last<<<gb_n, 256>>>(dout);
}

// round 17
// speedup vs baseline: 4.0331x; 1.0214x over previous
#include <cuda_runtime.h>
#include <cuda_bf16.h>
#include <stdint.h>

#define NV 100000
#define NE 600000
#define F 128
#define F2 256
#define NL 5

// ---------------- scratch ----------------
__device__ float Obuf[NV * F];                    // GEMM2 output (pre-BN h)
__device__ __nv_bfloat16 AggHi[(size_t)NV * F];   // aggregate, split bf16
__device__ __nv_bfloat16 AggLo[(size_t)NV * F];
__device__ float Sum_[F];
__device__ float Sq_[F];
__device__ float Scale_[F];
__device__ float Shift_[F];
__device__ __nv_bfloat16 W1Ht[NL * F2 * F];
__device__ __nv_bfloat16 W1Lt[NL * F2 * F];
__device__ __nv_bfloat16 W2Ht[NL * F * F2];
__device__ __nv_bfloat16 W2Lt[NL * F * F2];
// CSR by destination
__device__ int g_cnt[NV];
__device__ int g_cursor[NV];
__device__ int g_rowptr[NV + 1];
__device__ int g_bsum[128];
__device__ int g_boff[128];
__device__ int g_elist[NE];   // src | code<<20

__device__ __forceinline__ void splitbf(float v, __nv_bfloat16& h, __nv_bfloat16& lo) {
    h = __float2bfloat16(v);
    lo = __float2bfloat16(v - __bfloat162float(h));
}

__device__ __forceinline__ uint32_t pack2(float v0, float v1, uint32_t& lo_out) {
    __nv_bfloat16 h0, l0, h1, l1;
    splitbf(v0, h0, l0);
    splitbf(v1, h1, l1);
    lo_out = (uint32_t)__bfloat16_as_ushort(l0) |
             ((uint32_t)__bfloat16_as_ushort(l1) << 16);
    return (uint32_t)__bfloat16_as_ushort(h0) |
           ((uint32_t)__bfloat16_as_ushort(h1) << 16);
}

// ---------------- cp.async helpers ----------------
__device__ __forceinline__ uint32_t s2u(const void* p) {
    return (uint32_t)__cvta_generic_to_shared(p);
}

__device__ __forceinline__ void cpa16(uint32_t dst, const void* src) {
    asm volatile("cp.async.ca.shared.global [%0], [%1], 16;"
                 :: "r"(dst), "l"(src));
}

__device__ __forceinline__ void cpa16p(uint32_t dst, const void* src, int srcbytes) {
    asm volatile("cp.async.ca.shared.global [%0], [%1], 16, %2;"
                 :: "r"(dst), "l"(src), "r"(srcbytes));
}

#define CP_COMMIT() asm volatile("cp.async.commit_group;" ::: "memory")
#define CP_WAIT0()  asm volatile("cp.async.wait_group 0;" ::: "memory")

// ================= merged prep =================
__global__ void prep_all(const int* X, const float* XE1, const float* XE2,
                         const float* W1g, const float* W2g) {
    long long idx = (long long)blockIdx.x * blockDim.x + threadIdx.x;
    if (idx < (long long)NV * F) {
        int v = (int)(idx / F);
        int f = (int)(idx % F);
        int atom = X[2 * v];
        if (atom < 0) atom = 0;
        if (atom > 118) atom = 118;
        int chir = X[2 * v + 1];
        if (chir < 0) chir = 0;
        if (chir > 2) chir = 2;
        Obuf[idx] = XE1[atom * F + f] + XE2[chir * F + f];
    }
    if (idx < NL * F * F2) {
        int l = (int)(idx / (F * F2));
        int rem = (int)(idx % (F * F2));
        int k = rem / F2, n = rem % F2;
        __nv_bfloat16 h, lo;
        splitbf(W1g[idx], h, lo);
        W1Ht[((size_t)l * F2 + n) * F + k] = h;
        W1Lt[((size_t)l * F2 + n) * F + k] = lo;
        int k2 = rem / F, n2 = rem % F;
        splitbf(W2g[idx], h, lo);
        W2Ht[((size_t)l * F + n2) * F2 + k2] = h;
        W2Lt[((size_t)l * F + n2) * F2 + k2] = lo;
    }
    if (idx < NV) g_cnt[idx] = 0;
    if (idx < F) {
        Sum_[idx] = 0.f;
        Sq_[idx] = 0.f;
        Scale_[idx] = 1.f;
        Shift_[idx] = 0.f;
    }
}

// ================= CSR build =================
__global__ void z_count(const int* EI) {
    int e = blockIdx.x * blockDim.x + threadIdx.x;
    if (e >= NE) return;
    int d = EI[NE + e];
    if (d < 0) d = 0;
    if (d >= NV) d = NV - 1;
    atomicAdd(&g_cnt[d], 1);
}

__global__ void z_scan1() {
    __shared__ int s[1024];
    int t = threadIdx.x;
    int gi = blockIdx.x * 1024 + t;
    int v = (gi < NV) ? g_cnt[gi] : 0;
    s[t] = v;
    __syncthreads();
    for (int off = 1; off < 1024; off <<= 1) {
        int xv = 0;
        if (t >= off) xv = s[t - off];
        __syncthreads();
        s[t] += xv;
        __syncthreads();
    }
    if (gi < NV) g_cursor[gi] = s[t] - v;
    if (t == 1023) g_bsum[blockIdx.x] = s[t];
}

__global__ void z_scan2(int nb) {
    __shared__ int s[128];
    int t = threadIdx.x;
    int v = (t < nb) ? g_bsum[t] : 0;
    s[t] = v;
    __syncthreads();
    for (int off = 1; off < 128; off <<= 1) {
        int xv = 0;
        if (t >= off) xv = s[t - off];
        __syncthreads();
        s[t] += xv;
        __syncthreads();
    }
    g_boff[t] = s[t] - v;
    if (t == 0) g_rowptr[NV] = NE;
}

__global__ void z_scan3() {
    int i = blockIdx.x * blockDim.x + threadIdx.x;
    if (i >= NV) return;
    int rp = g_cursor[i] + g_boff[i >> 10];
    g_rowptr[i] = rp;
    g_cursor[i] = rp;
}

__global__ void z_scatter(const int* EI, const int* EA) {
    int e = blockIdx.x * blockDim.x + threadIdx.x;
    if (e >= NE) return;
    int d = EI[NE + e];
    if (d < 0) d = 0;
    if (d >= NV) d = NV - 1;
    int pos = atomicAdd(&g_cursor[d], 1);
    if (pos < 0) pos = 0;
    if (pos >= NE) pos = NE - 1;
    int s = EI[e];
    if (s < 0) s = 0;
    if (s >= NV) s = NV - 1;
    int b = EA[2 * e];
    if (b < 0) b = 0;
    if (b > 4) b = 4;
    int dr = EA[2 * e + 1];
    if (dr < 0) dr = 0;
    if (dr > 2) dr = 2;
    g_elist[pos] = s | ((b * 3 + dr) << 20);
}

// ================= aggregation with inline BN -> split bf16 output =================
__device__ __forceinline__ float4 bn4(float4 g, float4 sc, float4 sh, int dorelu) {
    float4 h;
    h.x = fmaf(g.x, sc.x, sh.x);
    h.y = fmaf(g.y, sc.y, sh.y);
    h.z = fmaf(g.z, sc.z, sh.z);
    h.w = fmaf(g.w, sc.w, sh.w);
    if (dorelu) {
        h.x = fmaxf(h.x, 0.f); h.y = fmaxf(h.y, 0.f);
        h.z = fmaxf(h.z, 0.f); h.w = fmaxf(h.w, 0.f);
    }
    return h;
}

__global__ void __launch_bounds__(256) k_agg(const float* __restrict__ EE1,
                                             const float* __restrict__ EE2,
                                             const float* __restrict__ EPS,
                                             int l, int dorelu) {
    __shared__ __align__(16) float etab[15 * F];
    int t = threadIdx.x;
    for (int j = t; j < 15 * F; j += 256) {
        int c = j >> 7, f = j & 127;
        etab[j] = EE1[(l * 5 + c / 3) * F + f] + EE2[(l * 3 + c % 3) * F + f];
    }
    __syncthreads();
    int gw = blockIdx.x * 8 + (t >> 5);
    int lane = t & 31;
    if (gw >= NV) return;
    float ep1 = 1.0f + EPS[l];
    const float4* Gv = (const float4*)Obuf;
    const float4* et = (const float4*)etab;
    float4 sc = ((const float4*)Scale_)[lane];
    float4 sh = ((const float4*)Shift_)[lane];

    float4 hn = bn4(Gv[(size_t)gw * 32 + lane], sc, sh, dorelu);
    float4 e0 = et[lane];
    float4 acc;
    acc.x = ep1 * hn.x + fmaxf(hn.x + e0.x, 0.f);
    acc.y = ep1 * hn.y + fmaxf(hn.y + e0.y, 0.f);
    acc.z = ep1 * hn.z + fmaxf(hn.z + e0.z, 0.f);
    acc.w = ep1 * hn.w + fmaxf(hn.w + e0.w, 0.f);

    int beg = g_rowptr[gw];
    int end = g_rowptr[gw + 1];
    if (beg < 0) beg = 0;
    if (end > NE) end = NE;
    for (int base = beg; base < end; base += 32) {
        int n = end - base;
        if (n > 32) n = 32;
        int p = 0;
        if (lane < n) p = g_elist[base + lane];
        int j = 0;
        for (; j + 4 <= n; j += 4) {
            int p0 = __shfl_sync(0xFFFFFFFF, p, j);
            int p1 = __shfl_sync(0xFFFFFFFF, p, j + 1);
            int p2 = __shfl_sync(0xFFFFFFFF, p, j + 2);
            int p3 = __shfl_sync(0xFFFFFFFF, p, j + 3);
            int s0 = p0 & 0xFFFFF, s1 = p1 & 0xFFFFF;
            int s2 = p2 & 0xFFFFF, s3 = p3 & 0xFFFFF;
            float4 g0 = __ldg(&Gv[(size_t)s0 * 32 + lane]);
            float4 g1v = __ldg(&Gv[(size_t)s1 * 32 + lane]);
            float4 g2v = __ldg(&Gv[(size_t)s2 * 32 + lane]);
            float4 g3 = __ldg(&Gv[(size_t)s3 * 32 + lane]);
            float4 h0 = bn4(g0, sc, sh, dorelu);
            float4 h1 = bn4(g1v, sc, sh, dorelu);
            float4 h2 = bn4(g2v, sc, sh, dorelu);
            float4 h3 = bn4(g3, sc, sh, dorelu);
            float4 e0v = et[((p0 >> 20) & 15) * 32 + lane];
            float4 e1v = et[((p1 >> 20) & 15) * 32 + lane];
            float4 e2v = et[((p2 >> 20) & 15) * 32 + lane];
            float4 e3v = et[((p3 >> 20) & 15) * 32 + lane];
            acc.x += fmaxf(h0.x + e0v.x, 0.f) + fmaxf(h1.x + e1v.x, 0.f) +
                     fmaxf(h2.x + e2v.x, 0.f) + fmaxf(h3.x + e3v.x, 0.f);
            acc.y += fmaxf(h0.y + e0v.y, 0.f) + fmaxf(h1.y + e1v.y, 0.f) +
                     fmaxf(h2.y + e2v.y, 0.f) + fmaxf(h3.y + e3v.y, 0.f);
            acc.z += fmaxf(h0.z + e0v.z, 0.f) + fmaxf(h1.z + e1v.z, 0.f) +
                     fmaxf(h2.z + e2v.z, 0.f) + fmaxf(h3.z + e3v.z, 0.f);
            acc.w += fmaxf(h0.w + e0v.w, 0.f) + fmaxf(h1.w + e1v.w, 0.f) +
                     fmaxf(h2.w + e2v.w, 0.f) + fmaxf(h3.w + e3v.w, 0.f);
        }
        for (; j < n; j++) {
            int pj = __shfl_sync(0xFFFFFFFF, p, j);
            int src = pj & 0xFFFFF;
            int code = (pj >> 20) & 15;
            float4 gs = __ldg(&Gv[(size_t)src * 32 + lane]);
            float4 hs = bn4(gs, sc, sh, dorelu);
            float4 ev = et[code * 32 + lane];
            acc.x += fmaxf(hs.x + ev.x, 0.f);
            acc.y += fmaxf(hs.y + ev.y, 0.f);
            acc.z += fmaxf(hs.z + ev.z, 0.f);
            acc.w += fmaxf(hs.w + ev.w, 0.f);
        }
    }
    uint32_t lo0, lo1;
    uint32_t hi0 = pack2(acc.x, acc.y, lo0);
    uint32_t hi1 = pack2(acc.z, acc.w, lo1);
    *(uint2*)((uint32_t*)AggHi + (size_t)gw * 64 + lane * 2) = make_uint2(hi0, hi1);
    *(uint2*)((uint32_t*)AggLo + (size_t)gw * 64 + lane * 2) = make_uint2(lo0, lo1);
}

// ================= BN finalize =================
__global__ void c_fin(const float* G, const float* B, int l) {
    int f = threadIdx.x;
    float mean = Sum_[f] / (float)NV;
    float var = Sq_[f] / (float)NV - mean * mean;
    if (var < 0.f) var = 0.f;
    float rstd = rsqrtf(var + 1e-5f);
    float sc = rstd * G[l * F + f];
    Scale_[f] = sc;
    Shift_[f] = B[l * F + f] - mean * sc;
    Sum_[f] = 0.f;
    Sq_[f] = 0.f;
}

__global__ void c_apply_last(float* dout) {
    long long idx = (long long)blockIdx.x * blockDim.x + threadIdx.x;
    if (idx >= (long long)NV * F) return;
    int f = (int)(idx % F);
    dout[idx] = Obuf[idx] * Scale_[f] + Shift_[f];
}

// ================= fused MLP: Obuf = (relu(Agg@W1+b1))@W2 + b2 (+BN stats) ==========
__device__ __forceinline__ void ldsm4(uint32_t& r0, uint32_t& r1, uint32_t& r2,
                                      uint32_t& r3, uint32_t a) {
    asm volatile("ldmatrix.sync.aligned.m8n8.x4.shared.b16 {%0,%1,%2,%3}, [%4];"
                 : "=r"(r0), "=r"(r1), "=r"(r2), "=r"(r3) : "r"(a));
}

__device__ __forceinline__ void mmabf(float* c,
                                      uint32_t a0, uint32_t a1, uint32_t a2, uint32_t a3,
                                      uint32_t b0, uint32_t b1) {
    asm volatile(
        "mma.sync.aligned.m16n8k16.row.col.f32.bf16.bf16.f32 "
        "{%0,%1,%2,%3},{%4,%5,%6,%7},{%8,%9},{%0,%1,%2,%3};"
        : "+f"(c[0]), "+f"(c[1]), "+f"(c[2]), "+f"(c[3])
        : "r"(a0), "r"(a1), "r"(a2), "r"(a3), "r"(b0), "r"(b1));
}

extern __shared__ __align__(16) char dsm[];

// smem layout in u32 units:
// phase1: AH [0,4352) AL [4352,8704) W1H [8704,26112) W1L [26112,43520)
// phase2: MidH [0,8448) MidL [8448,16896) W2H [16896,33792) W2L [33792,50688)
// total 50688 u32 = 202752 B
__global__ void __launch_bounds__(512) gf(const float* __restrict__ B1g,
                                          const float* __restrict__ B2g, int l) {
    uint32_t* S32 = (uint32_t*)dsm;
    __nv_bfloat16* Sbf = (__nv_bfloat16*)dsm;
    int tid = threadIdx.x;
    int lane = tid & 31, wid = tid >> 5;
    int row0 = blockIdx.x * 64;
    int wm = wid & 3, wn = wid >> 2;            // 4 x 4 warp grid
    int lrow = lane & 15, lkof = (lane >> 4) * 8;

    // ---- stage A (Agg) + W1 ----
    {
        const uint32_t* GH = (const uint32_t*)AggHi;
        const uint32_t* GL = (const uint32_t*)AggLo;
        for (int idx = tid; idx < 64 * 16; idx += 512) {
            int m = idx >> 4, c4 = (idx & 15) * 4;
            int row = row0 + m;
            int sb = (row < NV) ? 16 : 0;
            cpa16p(s2u(S32 + m * 68 + c4), GH + (size_t)row * 64 + c4, sb);
            cpa16p(s2u(S32 + 4352 + m * 68 + c4), GL + (size_t)row * 64 + c4, sb);
        }
        const uint32_t* WH = (const uint32_t*)W1Ht + (size_t)l * F2 * 64;
        const uint32_t* WL = (const uint32_t*)W1Lt + (size_t)l * F2 * 64;
        for (int idx = tid; idx < 256 * 16; idx += 512) {
            int n = idx >> 4, c4 = (idx & 15) * 4;
            cpa16(s2u(S32 + 8704 + n * 68 + c4), WH + n * 64 + c4);
            cpa16(s2u(S32 + 26112 + n * 68 + c4), WL + n * 64 + c4);
        }
    }
    CP_COMMIT();
    CP_WAIT0();
    __syncthreads();

    // ---- phase 1 MMA: Mid = Agg @ W1 (warp: 16 rows x 64 cols) ----
    const __nv_bfloat16* AHb = Sbf;
    const __nv_bfloat16* ALb = Sbf + 4352 * 2;
    const __nv_bfloat16* W1Hb = Sbf + 8704 * 2;
    const __nv_bfloat16* W1Lb = Sbf + 26112 * 2;

    float acc1[8][4];
#pragma unroll
    for (int i = 0; i < 8; i++)
#pragma unroll
        for (int j = 0; j < 4; j++) acc1[i][j] = 0.f;

#pragma unroll
    for (int ks = 0; ks < 8; ks++) {
        int kk = ks * 16 + lkof;
        uint32_t ah0, ah1, ah2, ah3, al0, al1, al2, al3;
        ldsm4(ah0, ah1, ah2, ah3, s2u(AHb + (wm * 16 + lrow) * 136 + kk));
        ldsm4(al0, al1, al2, al3, s2u(ALb + (wm * 16 + lrow) * 136 + kk));
#pragma unroll
        for (int np = 0; np < 4; np++) {
            int nrow = wn * 64 + np * 16 + lrow;
            uint32_t bh0, bh1, bh2, bh3, bl0, bl1, bl2, bl3;
            ldsm4(bh0, bh1, bh2, bh3, s2u(W1Hb + nrow * 136 + kk));
            ldsm4(bl0, bl1, bl2, bl3, s2u(W1Lb + nrow * 136 + kk));
            mmabf(acc1[2 * np], ah0, ah1, ah2, ah3, bh0, bh2);
            mmabf(acc1[2 * np], ah0, ah1, ah2, ah3, bl0, bl2);
            mmabf(acc1[2 * np], al0, al1, al2, al3, bh0, bh2);
            mmabf(acc1[2 * np + 1], ah0, ah1, ah2, ah3, bh1, bh3);
            mmabf(acc1[2 * np + 1], ah0, ah1, ah2, ah3, bl1, bl3);
            mmabf(acc1[2 * np + 1], al0, al1, al2, al3, bh1, bh3);
        }
    }
    __syncthreads();   // A/W1 reads complete; regions reusable

    // ---- write Mid (bias+relu+split) to smem; stage W2 concurrently ----
    {
        int r = lane >> 2, cp2 = (lane & 3) * 2;
        const float* bias = B1g + l * F2;
#pragma unroll
        for (int nt = 0; nt < 8; nt++) {
            int col = wn * 64 + nt * 8 + cp2;
            float b0 = __ldg(bias + col), b1v = __ldg(bias + col + 1);
#pragma unroll
            for (int half = 0; half < 2; half++) {
                int row = wm * 16 + r + half * 8;
                float v0 = fmaxf(acc1[nt][2 * half + 0] + b0, 0.f);
                float v1 = fmaxf(acc1[nt][2 * half + 1] + b1v, 0.f);
                uint32_t lw;
                uint32_t hw = pack2(v0, v1, lw);
                S32[row * 132 + (col >> 1)] = hw;            // MidH
                S32[8448 + row * 132 + (col >> 1)] = lw;     // MidL
            }
        }
        const uint32_t* WH = (const uint32_t*)W2Ht + (size_t)l * F * 128;
        const uint32_t* WL = (const uint32_t*)W2Lt + (size_t)l * F * 128;
        for (int idx = tid; idx < 128 * 32; idx += 512) {
            int n = idx >> 5, c4 = (idx & 31) * 4;
            cpa16(s2u(S32 + 16896 + n * 132 + c4), WH + n * 128 + c4);
            cpa16(s2u(S32 + 33792 + n * 132 + c4), WL + n * 128 + c4);
        }
    }
    CP_COMMIT();
    CP_WAIT0();
    __syncthreads();

    // ---- phase 2 MMA: Obuf = Mid @ W2 (warp: 16 rows x 32 cols, K=256) ----
    const __nv_bfloat16* MHb = Sbf;
    const __nv_bfloat16* MLb = Sbf + 8448 * 2;
    const __nv_bfloat16* W2Hb = Sbf + 16896 * 2;
    const __nv_bfloat16* W2Lb = Sbf + 33792 * 2;

    float acc2[4][4];
#pragma unroll
    for (int i = 0; i < 4; i++)
#pragma unroll
        for (int j = 0; j < 4; j++) acc2[i][j] = 0.f;

#pragma unroll
    for (int ks = 0; ks < 16; ks++) {
        int kk = ks * 16 + lkof;
        uint32_t ah0, ah1, ah2, ah3, al0, al1, al2, al3;
        ldsm4(ah0, ah1, ah2, ah3, s2u(MHb + (wm * 16 + lrow) * 264 + kk));
        ldsm4(al0, al1, al2, al3, s2u(MLb + (wm * 16 + lrow) * 264 + kk));
#pragma unroll
        for (int np = 0; np < 2; np++) {
            int nrow = wn * 32 + np * 16 + lrow;
            uint32_t bh0, bh1, bh2, bh3, bl0, bl1, bl2, bl3;
            ldsm4(bh0, bh1, bh2, bh3, s2u(W2Hb + nrow * 264 + kk));
            ldsm4(bl0, bl1, bl2, bl3, s2u(W2Lb + nrow * 264 + kk));
            mmabf(acc2[2 * np], ah0, ah1, ah2, ah3, bh0, bh2);
            mmabf(acc2[2 * np], ah0, ah1, ah2, ah3, bl0, bl2);
            mmabf(acc2[2 * np], al0, al1, al2, al3, bh0, bh2);
            mmabf(acc2[2 * np + 1], ah0, ah1, ah2, ah3, bh1, bh3);
            mmabf(acc2[2 * np + 1], ah0, ah1, ah2, ah3, bl1, bl3);
            mmabf(acc2[2 * np + 1], al0, al1, al2, al3, bh1, bh3);
        }
    }

    // ---- epilogue: bias + Obuf + BN stats ----
    const float* bias = B2g + l * F;
    int r = lane >> 2, cp2 = (lane & 3) * 2;
    float lsum[4][2], lsq[4][2];
#pragma unroll
    for (int nt = 0; nt < 4; nt++) {
        lsum[nt][0] = 0.f; lsum[nt][1] = 0.f;
        lsq[nt][0] = 0.f; lsq[nt][1] = 0.f;
    }
#pragma unroll
    for (int nt = 0; nt < 4; nt++) {
        int col = wn * 32 + nt * 8 + cp2;
        float b0 = __ldg(bias + col), b1v = __ldg(bias + col + 1);
#pragma unroll
        for (int half = 0; half < 2; half++) {
            int row = row0 + wm * 16 + r + half * 8;
            if (row < NV) {
                float2 o;
                o.x = acc2[nt][2 * half + 0] + b0;
                o.y = acc2[nt][2 * half + 1] + b1v;
                *(float2*)(Obuf + (size_t)row * F + col) = o;
                lsum[nt][0] += o.x; lsum[nt][1] += o.y;
                lsq[nt][0] += o.x * o.x; lsq[nt][1] += o.y * o.y;
            }
        }
    }
#pragma unroll
    for (int nt = 0; nt < 4; nt++) {
#pragma unroll
        for (int c = 0; c < 2; c++) {
#pragma unroll
            for (int off = 4; off < 32; off <<= 1) {
                lsum[nt][c] += __shfl_xor_sync(0xFFFFFFFF, lsum[nt][c], off);
                lsq[nt][c] += __shfl_xor_sync(0xFFFFFFFF, lsq[nt][c], off);
            }
        }
    }
    if (lane < 4) {
#pragma unroll
        for (int nt = 0; nt < 4; nt++) {
            int col = wn * 32 + nt * 8 + lane * 2;
            atomicAdd(&Sum_[col], lsum[nt][0]);
            atomicAdd(&Sum_[col + 1], lsum[nt][1]);
            atomicAdd(&Sq_[col], lsq[nt][0]);
            atomicAdd(&Sq_[col + 1], lsq[nt][1]);
        }
    }
}

// ================= launch =================
extern "C" void kernel_launch(void* const* d_in, const int* in_sizes, int n_in,
                              void* d_out, int out_size) {
    const int*   X   = (const int*)d_in[0];
    const int*   EI  = (const int*)d_in[1];
    const int*   EA  = (const int*)d_in[2];
    const float* XE1 = (const float*)d_in[3];
    const float* XE2 = (const float*)d_in[4];
    const float* EE1 = (const float*)d_in[5];
    const float* EE2 = (const float*)d_in[6];
    const float* W1g = (const float*)d_in[7];
    const float* B1g = (const float*)d_in[8];
    const float* W2g = (const float*)d_in[9];
    const float* B2g = (const float*)d_in[10];
    const float* EPS = (const float*)d_in[11];
    const float* G   = (const float*)d_in[12];
    const float* B   = (const float*)d_in[13];
    float* dout = (float*)d_out;

    const int SMG = 50688 * 4;  // 202752 B
    cudaFuncSetAttribute(gf, cudaFuncAttributeMaxDynamicSharedMemorySize, SMG);

    long long nvf = (long long)NV * F;
    int gb_n = (int)((nvf + 255) / 256);

    prep_all<<<gb_n, 256>>>(X, XE1, XE2, W1g, W2g);
    z_count<<<(NE + 255) / 256, 256>>>(EI);
    int nb = (NV + 1023) / 1024;  // 98
    z_scan1<<<nb, 1024>>>();
    z_scan2<<<1, 128>>>(nb);
    z_scan3<<<(NV + 255) / 256, 256>>>();
    z_scatter<<<(NE + 255) / 256, 256>>>(EI, EA);

    int gridf = (NV + 63) / 64;  // 1563
    int gagg = (NV + 7) / 8;     // 12500
    for (int l = 0; l < NL; l++) {
        k_agg<<<gagg, 256>>>(EE1, EE2, EPS, l, l > 0 ? 1 : 0);
        gf<<<gridf, 512, SMG>>>(B1g, B2g, l);
        c_fin<<<1, 128>>>(G, B, l);
    }
    c_apply_last<<<gb_n, 256>>>(dout);
}